// round 1
// baseline (speedup 1.0000x reference)
#include <cuda_runtime.h>
#include <math.h>

#define NB 2
#define NT 2048
#define ND 2048
#define NH 16
#define NKV 4
#define HD 128

// ---------------- scratch (static device allocations are allowed) -------------
static __device__ float g_qkv[(size_t)NB * NT * 3072];       // [4096, 3072]
static __device__ float g_q[(size_t)NB * NH * NT * HD];      // [b,h,t,d]
static __device__ float g_k[(size_t)NB * NKV * NT * HD];     // [b,kv,t,d]
static __device__ float g_v[(size_t)NB * NKV * NT * HD];     // [b,kv,t,d]
static __device__ float g_y[(size_t)NB * NT * ND];           // [b,t,h*128+d]
static __device__ float g_cos[NT * 64];
static __device__ float g_sin[NT * 64];

// ---------------- RoPE table (double precision, tiny) -------------------------
__global__ void rope_table_kernel() {
    int t = blockIdx.x;
    int i = threadIdx.x;  // 0..63
    double f = exp(-((double)(2 * i) / 128.0) * log(10000.0));
    double a = (double)t * f;
    g_cos[t * 64 + i] = (float)cos(a);
    g_sin[t * 64 + i] = (float)sin(a);
}

// ---------------- tiled fp32 GEMM body: C += A(128 rows) x W(128 rows)^T ------
// A: [.,2048] row-major (rows m0..m0+127), W: 128x2048 row-major tile,
// C indexed as C[(m0+r)*ldc + c] (C already column-offset by caller).
__device__ __forceinline__ void gemm_body(const float* __restrict__ A,
                                          const float* __restrict__ W,
                                          float* __restrict__ C, int ldc) {
    __shared__ float As[16][132];
    __shared__ float Ws[16][132];
    const int K = 2048;
    int tid = threadIdx.x;
    int m0 = blockIdx.x * 128;
    int ty = tid >> 4, tx = tid & 15;
    int lrow = tid >> 2, lq = tid & 3;

    float acc[8][8];
#pragma unroll
    for (int i = 0; i < 8; i++)
#pragma unroll
        for (int j = 0; j < 8; j++) acc[i][j] = 0.f;

    for (int k0 = 0; k0 < K; k0 += 16) {
#pragma unroll
        for (int h = 0; h < 2; h++) {
            int row = lrow + h * 64;
            float4 a4 = *(const float4*)(A + (size_t)(m0 + row) * K + k0 + lq * 4);
            As[lq * 4 + 0][row] = a4.x;
            As[lq * 4 + 1][row] = a4.y;
            As[lq * 4 + 2][row] = a4.z;
            As[lq * 4 + 3][row] = a4.w;
            float4 w4 = *(const float4*)(W + (size_t)row * K + k0 + lq * 4);
            Ws[lq * 4 + 0][row] = w4.x;
            Ws[lq * 4 + 1][row] = w4.y;
            Ws[lq * 4 + 2][row] = w4.z;
            Ws[lq * 4 + 3][row] = w4.w;
        }
        __syncthreads();
#pragma unroll
        for (int kk = 0; kk < 16; kk++) {
            float4 a0 = *(const float4*)&As[kk][ty * 8];
            float4 a1 = *(const float4*)&As[kk][ty * 8 + 4];
            float4 b0 = *(const float4*)&Ws[kk][tx * 8];
            float4 b1 = *(const float4*)&Ws[kk][tx * 8 + 4];
            float a[8] = {a0.x, a0.y, a0.z, a0.w, a1.x, a1.y, a1.z, a1.w};
            float w[8] = {b0.x, b0.y, b0.z, b0.w, b1.x, b1.y, b1.z, b1.w};
#pragma unroll
            for (int i = 0; i < 8; i++)
#pragma unroll
                for (int j = 0; j < 8; j++) acc[i][j] = fmaf(a[i], w[j], acc[i][j]);
        }
        __syncthreads();
    }
#pragma unroll
    for (int i = 0; i < 8; i++)
#pragma unroll
        for (int j = 0; j < 8; j++)
            C[(size_t)(m0 + ty * 8 + i) * ldc + tx * 8 + j] = acc[i][j];
}

// grid: (32, 24). y-tiles 0..15 -> Q, 16..19 -> K, 20..23 -> V
__global__ __launch_bounds__(256) void gemm_qkv_kernel(const float* __restrict__ x,
                                                       const float* __restrict__ wq,
                                                       const float* __restrict__ wk,
                                                       const float* __restrict__ wv) {
    int nt = blockIdx.y;
    const float* W;
    int c0;
    if (nt < 16) {
        W = wq + (size_t)nt * 128 * 2048;
        c0 = nt * 128;
    } else if (nt < 20) {
        W = wk + (size_t)(nt - 16) * 128 * 2048;
        c0 = 2048 + (nt - 16) * 128;
    } else {
        W = wv + (size_t)(nt - 20) * 128 * 2048;
        c0 = 2560 + (nt - 20) * 128;
    }
    gemm_body(x, W, g_qkv + c0, 3072);
}

// grid: (32, 16)
__global__ __launch_bounds__(256) void gemm_out_kernel(const float* __restrict__ wo,
                                                       float* __restrict__ out) {
    const float* W = wo + (size_t)blockIdx.y * 128 * 2048;
    gemm_body(g_y, W, out + blockIdx.y * 128, 2048);
}

// ---------------- RoPE + RMSNorm + transpose ---------------------------------
// grid (NB*NT, 24), 128 threads. y: 0..15 Q head, 16..19 K head, 20..23 V copy
__global__ __launch_bounds__(128) void rope_norm_kernel(const float* __restrict__ qnw,
                                                        const float* __restrict__ knw) {
    int m = blockIdx.x;                 // b*T + t
    int r = blockIdx.y;
    int d = threadIdx.x;                // 0..127
    int t = m & (NT - 1);
    int b = m >> 11;
    const float* base = g_qkv + (size_t)m * 3072;

    if (r >= 20) {  // V: transpose only
        int kv = r - 20;
        g_v[(((size_t)(b * NKV + kv)) * NT + t) * HD + d] = base[2560 + kv * 128 + d];
        return;
    }

    float x, w;
    float* dst;
    if (r < 16) {
        x = base[r * 128 + d];
        w = qnw[d];
        dst = g_q + (((size_t)(b * NH + r)) * NT + t) * HD;
    } else {
        int kv = r - 16;
        x = base[2048 + kv * 128 + d];
        w = knw[d];
        dst = g_k + (((size_t)(b * NKV + kv)) * NT + t) * HD;
    }

    int i = d >> 1;
    float c = g_cos[t * 64 + i];
    float s = g_sin[t * 64 + i];
    float part = __shfl_xor_sync(0xffffffffu, x, 1);
    float o = (d & 1) ? fmaf(part, s, x * c) : fmaf(x, c, -part * s);

    // block-wide sum of squares over 128 lanes
    __shared__ float red[4];
    float sq = o * o;
#pragma unroll
    for (int off = 16; off >= 1; off >>= 1) sq += __shfl_xor_sync(0xffffffffu, sq, off);
    if ((d & 31) == 0) red[d >> 5] = sq;
    __syncthreads();
    float var = (red[0] + red[1] + red[2] + red[3]) * (1.0f / 128.0f);
    dst[d] = o * rsqrtf(var + 1.1920929e-7f) * w;
}

// ---------------- flash attention (fp32, causal) -----------------------------
#define QP 129
#define KP 129
#define VP 132
#define PP 68
#define FLASH_SMEM ((64 * QP + 64 * KP + 64 * VP + 64 * PP) * 4)

__global__ __launch_bounds__(256) void flash_kernel() {
    extern __shared__ float sm[];
    float* Qs = sm;                    // [64][129]
    float* Ks = Qs + 64 * QP;          // [64][129]
    float* Vs = Ks + 64 * KP;          // [64][132]
    float* Ps = Vs + 64 * VP;          // [64][68]

    int qt = blockIdx.x;               // q tile (0..31)
    int h = blockIdx.y;                // head
    int b = blockIdx.z;                // batch
    int kvh = h >> 2;
    const float* Qb = g_q + (((size_t)(b * NH + h)) * NT + qt * 64) * HD;
    const float* Kb = g_k + ((size_t)(b * NKV + kvh)) * NT * HD;
    const float* Vb = g_v + ((size_t)(b * NKV + kvh)) * NT * HD;

    int tid = threadIdx.x;
    int ty = tid >> 4, tx = tid & 15;  // rows ty*4.., S-cols tx*4.., O-cols tx+16c

    // load Q tile
    for (int i = tid; i < 64 * 32; i += 256) {
        int row = i >> 5, c4 = i & 31;
        float4 v = ((const float4*)Qb)[i];
        float* dq = Qs + row * QP + c4 * 4;
        dq[0] = v.x; dq[1] = v.y; dq[2] = v.z; dq[3] = v.w;
    }

    float acc[4][8];
    float m_i[4], l_i[4];
#pragma unroll
    for (int i = 0; i < 4; i++) {
        m_i[i] = -INFINITY;
        l_i[i] = 0.f;
#pragma unroll
        for (int j = 0; j < 8; j++) acc[i][j] = 0.f;
    }

    const float scale = 0.08838834764831845f;  // 1/sqrt(128)
    int nkt = qt + 1;
    for (int kt = 0; kt < nkt; kt++) {
        __syncthreads();
        // load K, V tiles
        for (int i = tid; i < 64 * 32; i += 256) {
            int row = i >> 5, c4 = i & 31;
            float4 kv4 = ((const float4*)(Kb + (size_t)kt * 64 * HD))[i];
            float* dk = Ks + row * KP + c4 * 4;
            dk[0] = kv4.x; dk[1] = kv4.y; dk[2] = kv4.z; dk[3] = kv4.w;
            float4 vv4 = ((const float4*)(Vb + (size_t)kt * 64 * HD))[i];
            *(float4*)(Vs + row * VP + c4 * 4) = vv4;
        }
        __syncthreads();

        // S = scale * Q K^T (4x4 per thread)
        float s[4][4];
#pragma unroll
        for (int i = 0; i < 4; i++)
#pragma unroll
            for (int j = 0; j < 4; j++) s[i][j] = 0.f;
        for (int k = 0; k < HD; k++) {
            float a0 = Qs[(ty * 4 + 0) * QP + k];
            float a1 = Qs[(ty * 4 + 1) * QP + k];
            float a2 = Qs[(ty * 4 + 2) * QP + k];
            float a3 = Qs[(ty * 4 + 3) * QP + k];
            float b0 = Ks[(tx * 4 + 0) * KP + k];
            float b1 = Ks[(tx * 4 + 1) * KP + k];
            float b2 = Ks[(tx * 4 + 2) * KP + k];
            float b3 = Ks[(tx * 4 + 3) * KP + k];
            s[0][0] = fmaf(a0, b0, s[0][0]); s[0][1] = fmaf(a0, b1, s[0][1]);
            s[0][2] = fmaf(a0, b2, s[0][2]); s[0][3] = fmaf(a0, b3, s[0][3]);
            s[1][0] = fmaf(a1, b0, s[1][0]); s[1][1] = fmaf(a1, b1, s[1][1]);
            s[1][2] = fmaf(a1, b2, s[1][2]); s[1][3] = fmaf(a1, b3, s[1][3]);
            s[2][0] = fmaf(a2, b0, s[2][0]); s[2][1] = fmaf(a2, b1, s[2][1]);
            s[2][2] = fmaf(a2, b2, s[2][2]); s[2][3] = fmaf(a2, b3, s[2][3]);
            s[3][0] = fmaf(a3, b0, s[3][0]); s[3][1] = fmaf(a3, b1, s[3][1]);
            s[3][2] = fmaf(a3, b2, s[3][2]); s[3][3] = fmaf(a3, b3, s[3][3]);
        }

        bool diag = (kt == qt);
#pragma unroll
        for (int i = 0; i < 4; i++) {
            int qidx = qt * 64 + ty * 4 + i;
            float mnew = -INFINITY;
#pragma unroll
            for (int j = 0; j < 4; j++) {
                s[i][j] *= scale;
                if (diag && (kt * 64 + tx * 4 + j > qidx)) s[i][j] = -INFINITY;
                mnew = fmaxf(mnew, s[i][j]);
            }
#pragma unroll
            for (int off = 8; off >= 1; off >>= 1)
                mnew = fmaxf(mnew, __shfl_xor_sync(0xffffffffu, mnew, off, 16));
            float mo = m_i[i];
            float mn = fmaxf(mo, mnew);
            float corr = __expf(mo - mn);  // exp(-inf)=0 on first tile
            float lsum = 0.f;
#pragma unroll
            for (int j = 0; j < 4; j++) {
                float p = __expf(s[i][j] - mn);
                Ps[(ty * 4 + i) * PP + tx * 4 + j] = p;
                lsum += p;
            }
#pragma unroll
            for (int off = 8; off >= 1; off >>= 1)
                lsum += __shfl_xor_sync(0xffffffffu, lsum, off, 16);
            l_i[i] = l_i[i] * corr + lsum;
            m_i[i] = mn;
#pragma unroll
            for (int c = 0; c < 8; c++) acc[i][c] *= corr;
        }
        __syncthreads();

        // O += P V (cols tx + 16*c: conflict-free Vs reads)
        for (int k = 0; k < 64; k++) {
            float p0 = Ps[(ty * 4 + 0) * PP + k];
            float p1 = Ps[(ty * 4 + 1) * PP + k];
            float p2 = Ps[(ty * 4 + 2) * PP + k];
            float p3 = Ps[(ty * 4 + 3) * PP + k];
#pragma unroll
            for (int c = 0; c < 8; c++) {
                float v = Vs[k * VP + tx + 16 * c];
                acc[0][c] = fmaf(p0, v, acc[0][c]);
                acc[1][c] = fmaf(p1, v, acc[1][c]);
                acc[2][c] = fmaf(p2, v, acc[2][c]);
                acc[3][c] = fmaf(p3, v, acc[3][c]);
            }
        }
    }

    // normalize + write y[b, q, h*128 + col]
#pragma unroll
    for (int i = 0; i < 4; i++) {
        float inv = 1.0f / l_i[i];
        size_t row = (size_t)(b * NT + qt * 64 + ty * 4 + i) * ND + h * 128;
#pragma unroll
        for (int c = 0; c < 8; c++) g_y[row + tx + 16 * c] = acc[i][c] * inv;
    }
}

// ---------------- launch ------------------------------------------------------
extern "C" void kernel_launch(void* const* d_in, const int* in_sizes, int n_in,
                              void* d_out, int out_size) {
    const float* x   = (const float*)d_in[0];
    const float* wq  = (const float*)d_in[1];
    const float* wk  = (const float*)d_in[2];
    const float* wv  = (const float*)d_in[3];
    const float* wo  = (const float*)d_in[4];
    const float* qnw = (const float*)d_in[5];
    const float* knw = (const float*)d_in[6];
    float* out = (float*)d_out;

    cudaFuncSetAttribute(flash_kernel, cudaFuncAttributeMaxDynamicSharedMemorySize,
                         FLASH_SMEM);

    rope_table_kernel<<<NT, 64>>>();
    gemm_qkv_kernel<<<dim3(32, 24), 256>>>(x, wq, wk, wv);
    rope_norm_kernel<<<dim3(NB * NT, 24), 128>>>(qnw, knw);
    flash_kernel<<<dim3(NT / 64, NH, NB), 256, FLASH_SMEM>>>();
    gemm_out_kernel<<<dim3(32, 16), 256>>>(wo, out);
}

// round 3
// speedup vs baseline: 2.3146x; 2.3146x over previous
#include <cuda_runtime.h>
#include <cuda_bf16.h>
#include <math.h>
#include <cstdint>

#define NB 2
#define NT 2048
#define ND 2048
#define NH 16
#define NKV 4
#define HD 128

typedef __nv_bfloat16 bf16;

// ---------------- scratch -----------------------------------------------------
static __device__ float g_qkv[(size_t)NB * NT * 3072];
static __device__ float g_cos[NT * 64];
static __device__ float g_sin[NT * 64];
static __device__ bf16 g_xh[(size_t)NB * NT * ND], g_xl[(size_t)NB * NT * ND];
static __device__ bf16 g_wh[(size_t)3072 * 2048], g_wl[(size_t)3072 * 2048];
static __device__ bf16 g_woh[(size_t)2048 * 2048], g_wol[(size_t)2048 * 2048];
static __device__ bf16 g_yh[(size_t)NB * NT * ND], g_yl[(size_t)NB * NT * ND];
static __device__ bf16 g_Qh[(size_t)NB * NH * NT * HD], g_Ql[(size_t)NB * NH * NT * HD];
static __device__ bf16 g_Kh[(size_t)NB * NKV * NT * HD], g_Kl[(size_t)NB * NKV * NT * HD];
static __device__ bf16 g_Vh[(size_t)NB * NKV * NT * HD], g_Vl[(size_t)NB * NKV * NT * HD];

// ---------------- PTX helpers (sm_80-compatible, no 'a' features) -------------
__device__ __forceinline__ uint32_t smem_u32(const void* p) {
    uint32_t a;
    asm("{ .reg .u64 t; cvta.to.shared.u64 t, %1; cvt.u32.u64 %0, t; }" : "=r"(a) : "l"(p));
    return a;
}
#define CP_ASYNC16(dst, src)                                                   \
    asm volatile("cp.async.cg.shared.global [%0], [%1], 16;"                   \
                 :: "r"(dst), "l"(src) : "memory")
#define CP_COMMIT() asm volatile("cp.async.commit_group;" ::: "memory")
#define CP_WAIT0()  asm volatile("cp.async.wait_group 0;" ::: "memory")
#define LDSM_X4(r0, r1, r2, r3, addr)                                          \
    asm volatile("ldmatrix.sync.aligned.m8n8.x4.shared.b16 {%0,%1,%2,%3}, [%4];" \
                 : "=r"(r0), "=r"(r1), "=r"(r2), "=r"(r3) : "r"(addr))
#define LDSM_X4_T(r0, r1, r2, r3, addr)                                        \
    asm volatile("ldmatrix.sync.aligned.m8n8.x4.trans.shared.b16 {%0,%1,%2,%3}, [%4];" \
                 : "=r"(r0), "=r"(r1), "=r"(r2), "=r"(r3) : "r"(addr))
#define MMA16816(d, a0, a1, a2, a3, b0, b1)                                    \
    asm volatile("mma.sync.aligned.m16n8k16.row.col.f32.bf16.bf16.f32 "        \
                 "{%0,%1,%2,%3}, {%4,%5,%6,%7}, {%8,%9}, {%0,%1,%2,%3};"       \
                 : "+f"((d)[0]), "+f"((d)[1]), "+f"((d)[2]), "+f"((d)[3])      \
                 : "r"(a0), "r"(a1), "r"(a2), "r"(a3), "r"(b0), "r"(b1))

__device__ __forceinline__ uint32_t pack_bf16(float a, float b) {
    __nv_bfloat162 t = __floats2bfloat162_rn(a, b);
    return *(uint32_t*)&t;
}

// ---------------- RoPE table --------------------------------------------------
__global__ void rope_table_kernel() {
    int t = blockIdx.x;
    int i = threadIdx.x;  // 0..63
    double f = exp(-((double)(2 * i) / 128.0) * log(10000.0));
    double a = (double)t * f;
    g_cos[t * 64 + i] = (float)cos(a);
    g_sin[t * 64 + i] = (float)sin(a);
}

// ---------------- fp32 -> bf16 hi/lo split ------------------------------------
__global__ __launch_bounds__(256) void split_kernel(const float* __restrict__ src,
                                                    int sel, size_t doff, int n) {
    int i = (blockIdx.x * 256 + threadIdx.x) * 4;
    if (i >= n) return;
    bf16 *H, *L;
    if (sel == 0)      { H = g_xh;  L = g_xl; }
    else if (sel == 1) { H = g_wh;  L = g_wl; }
    else               { H = g_woh; L = g_wol; }
    H += doff + i; L += doff + i;
    float4 v = *(const float4*)(src + i);
    float vv[4] = {v.x, v.y, v.z, v.w};
    bf16 hv[4], lv[4];
#pragma unroll
    for (int e = 0; e < 4; e++) {
        hv[e] = __float2bfloat16(vv[e]);
        lv[e] = __float2bfloat16(vv[e] - __bfloat162float(hv[e]));
    }
    *(__nv_bfloat162*)(H)     = __halves2bfloat162(hv[0], hv[1]);
    *(__nv_bfloat162*)(H + 2) = __halves2bfloat162(hv[2], hv[3]);
    *(__nv_bfloat162*)(L)     = __halves2bfloat162(lv[0], lv[1]);
    *(__nv_bfloat162*)(L + 2) = __halves2bfloat162(lv[2], lv[3]);
}

// ---------------- split-bf16 GEMM via mma.sync --------------------------------
// C[m][n] = sum_k A[m][k]*B[n][k]. CTA tile 128x128, K-chunk 32, double-buffered
// cp.async. 256 thr = 8 warps (4M x 2N), warp tile 32x64.
// smem per buffer: Ah,Al,Bh,Bl each [128][40] bf16 (stride 40 elem = 80B, LDSM
// conflict-free); buffer = 40960B, two buffers.
#define GEMM_SMEM (2 * 40960)

__global__ __launch_bounds__(256) void gemm_mma_kernel(int mode, float* __restrict__ Cout) {
    extern __shared__ char smem[];
    const bf16 *Ah, *Al, *Bh, *Bl;
    float* C;
    int ldc;
    if (mode == 0) { Ah = g_xh; Al = g_xl; Bh = g_wh;  Bl = g_wl;  C = g_qkv; ldc = 3072; }
    else           { Ah = g_yh; Al = g_yl; Bh = g_woh; Bl = g_wol; C = Cout;  ldc = 2048; }
    uint32_t sb = smem_u32(smem);
    int tid = threadIdx.x, lane = tid & 31, wid = tid >> 5;
    int wm = wid >> 1, wn = wid & 1;
    int m0 = blockIdx.x * 128, n0 = blockIdx.y * 128;

    int row = tid >> 1, half = tid & 1;
    size_t aoff0 = (size_t)(m0 + row) * 2048 + half * 16;
    size_t boff0 = (size_t)(n0 + row) * 2048 + half * 16;
    uint32_t dst0 = sb + row * 80 + half * 32;

    float acc[2][8][4];
#pragma unroll
    for (int mi = 0; mi < 2; mi++)
#pragma unroll
        for (int t = 0; t < 8; t++)
#pragma unroll
            for (int c = 0; c < 4; c++) acc[mi][t][c] = 0.f;

#define GEMM_PREFETCH(c, bsel) do {                                            \
    uint32_t d = dst0 + (bsel) * 40960;                                        \
    size_t ao = aoff0 + (c) * 32, bo = boff0 + (c) * 32;                       \
    CP_ASYNC16(d,             (const void*)(Ah + ao));                         \
    CP_ASYNC16(d + 16,        (const void*)(Ah + ao + 8));                     \
    CP_ASYNC16(d + 10240,     (const void*)(Al + ao));                         \
    CP_ASYNC16(d + 10256,     (const void*)(Al + ao + 8));                     \
    CP_ASYNC16(d + 20480,     (const void*)(Bh + bo));                         \
    CP_ASYNC16(d + 20496,     (const void*)(Bh + bo + 8));                     \
    CP_ASYNC16(d + 30720,     (const void*)(Bl + bo));                         \
    CP_ASYNC16(d + 30736,     (const void*)(Bl + bo + 8));                     \
} while (0)

    GEMM_PREFETCH(0, 0);
    CP_COMMIT();

    int r16 = lane & 15;
    uint32_t cby = (lane >> 4) * 16;  // (lane/16)*8 elems in bytes

    for (int c = 0; c < 64; c++) {
        CP_WAIT0();
        __syncthreads();
        if (c < 63) { GEMM_PREFETCH(c + 1, (c + 1) & 1); CP_COMMIT(); }
        uint32_t base = sb + (c & 1) * 40960;
#pragma unroll
        for (int ks = 0; ks < 2; ks++) {
            uint32_t ahf[2][4], alf[2][4], bhf[4][4], blf[4][4];
#pragma unroll
            for (int mi = 0; mi < 2; mi++) {
                uint32_t ad = base + ((wm * 32 + mi * 16 + r16) * 40 + ks * 16) * 2 + cby;
                LDSM_X4(ahf[mi][0], ahf[mi][1], ahf[mi][2], ahf[mi][3], ad);
                LDSM_X4(alf[mi][0], alf[mi][1], alf[mi][2], alf[mi][3], ad + 10240);
            }
#pragma unroll
            for (int g = 0; g < 4; g++) {
                uint32_t bd = base + 20480 + ((wn * 64 + g * 16 + r16) * 40 + ks * 16) * 2 + cby;
                LDSM_X4(bhf[g][0], bhf[g][1], bhf[g][2], bhf[g][3], bd);
                LDSM_X4(blf[g][0], blf[g][1], blf[g][2], blf[g][3], bd + 10240);
            }
#pragma unroll
            for (int mi = 0; mi < 2; mi++)
#pragma unroll
                for (int t = 0; t < 8; t++) {
                    int g = t >> 1, s = t & 1;
                    uint32_t bh0 = bhf[g][s], bh1 = bhf[g][s + 2];
                    uint32_t bl0 = blf[g][s], bl1 = blf[g][s + 2];
                    MMA16816(acc[mi][t], ahf[mi][0], ahf[mi][1], ahf[mi][2], ahf[mi][3], bh0, bh1);
                    MMA16816(acc[mi][t], ahf[mi][0], ahf[mi][1], ahf[mi][2], ahf[mi][3], bl0, bl1);
                    MMA16816(acc[mi][t], alf[mi][0], alf[mi][1], alf[mi][2], alf[mi][3], bh0, bh1);
                }
        }
        __syncthreads();
    }

#pragma unroll
    for (int mi = 0; mi < 2; mi++)
#pragma unroll
        for (int t = 0; t < 8; t++) {
            int r = m0 + wm * 32 + mi * 16 + (lane >> 2);
            int cc = n0 + wn * 64 + t * 8 + (lane & 3) * 2;
            *(float2*)&C[(size_t)r * ldc + cc]       = make_float2(acc[mi][t][0], acc[mi][t][1]);
            *(float2*)&C[(size_t)(r + 8) * ldc + cc] = make_float2(acc[mi][t][2], acc[mi][t][3]);
        }
}

// ---------------- RoPE + RMSNorm + transpose + split -------------------------
__global__ __launch_bounds__(128) void rope_norm_kernel(const float* __restrict__ qnw,
                                                        const float* __restrict__ knw) {
    int m = blockIdx.x;
    int r = blockIdx.y;
    int d = threadIdx.x;
    int t = m & (NT - 1);
    int b = m >> 11;
    const float* base = g_qkv + (size_t)m * 3072;

    if (r >= 20) {  // V: split only
        int kv = r - 20;
        size_t idx = (((size_t)(b * NKV + kv)) * NT + t) * HD + d;
        float v = base[2560 + kv * 128 + d];
        bf16 h = __float2bfloat16(v);
        g_Vh[idx] = h;
        g_Vl[idx] = __float2bfloat16(v - __bfloat162float(h));
        return;
    }
    float x, w;
    bf16 *dh, *dl;
    size_t idx;
    if (r < 16) {
        x = base[r * 128 + d];
        w = qnw[d];
        idx = (((size_t)(b * NH + r)) * NT + t) * HD + d;
        dh = g_Qh; dl = g_Ql;
    } else {
        int kv = r - 16;
        x = base[2048 + kv * 128 + d];
        w = knw[d];
        idx = (((size_t)(b * NKV + kv)) * NT + t) * HD + d;
        dh = g_Kh; dl = g_Kl;
    }
    int i = d >> 1;
    float c = g_cos[t * 64 + i];
    float s = g_sin[t * 64 + i];
    float part = __shfl_xor_sync(0xffffffffu, x, 1);
    float o = (d & 1) ? fmaf(part, s, x * c) : fmaf(x, c, -part * s);

    __shared__ float red[4];
    float sq = o * o;
#pragma unroll
    for (int off = 16; off >= 1; off >>= 1) sq += __shfl_xor_sync(0xffffffffu, sq, off);
    if ((d & 31) == 0) red[d >> 5] = sq;
    __syncthreads();
    float var = (red[0] + red[1] + red[2] + red[3]) * (1.0f / 128.0f);
    float out = o * rsqrtf(var + 1.1920929e-7f) * w;
    bf16 h = __float2bfloat16(out);
    dh[idx] = h;
    dl[idx] = __float2bfloat16(out - __bfloat162float(h));
}

// ---------------- flash attention via mma.sync (split bf16) -------------------
// CTA: 128 thr = 4 warps, BQ=64 (16 rows/warp), BK=64, hd=128.
// smem: Qh,Ql,Kh,Kl,Vh,Vl each [64][136] bf16 (stride 272B, LDSM conflict-free)
#define FROW 272                     // row stride bytes
#define FTILE (64 * FROW)            // 17408 B per tensor
#define FLASH_SMEM (6 * FTILE)

__global__ __launch_bounds__(128, 2) void flash_kernel() {
    extern __shared__ char smem[];
    uint32_t sb = smem_u32(smem);
    const uint32_t SQ = 0, SK = 2 * FTILE, SV = 4 * FTILE;

    int qt = blockIdx.x, h = blockIdx.y, b = blockIdx.z;
    int kvh = h >> 2;
    int tid = threadIdx.x, lane = tid & 31, w = tid >> 5;

    const bf16* Qhg = g_Qh + ((size_t)(b * NH + h) * NT + qt * 64) * HD;
    const bf16* Qlg = g_Ql + ((size_t)(b * NH + h) * NT + qt * 64) * HD;
    const bf16* Khg = g_Kh + (size_t)(b * NKV + kvh) * NT * HD;
    const bf16* Klg = g_Kl + (size_t)(b * NKV + kvh) * NT * HD;
    const bf16* Vhg = g_Vh + (size_t)(b * NKV + kvh) * NT * HD;
    const bf16* Vlg = g_Vl + (size_t)(b * NKV + kvh) * NT * HD;

    // load Q (once)
#pragma unroll
    for (int i = 0; i < 8; i++) {
        int linear = i * 128 + tid;
        int r = linear >> 4, c = linear & 15;
        uint32_t d = sb + SQ + r * FROW + c * 16;
        CP_ASYNC16(d,         (const void*)(Qhg + r * HD + c * 8));
        CP_ASYNC16(d + FTILE, (const void*)(Qlg + r * HD + c * 8));
    }
    CP_COMMIT();

    float o[16][4];
#pragma unroll
    for (int t = 0; t < 16; t++)
#pragma unroll
        for (int c = 0; c < 4; c++) o[t][c] = 0.f;
    float m0r = -INFINITY, m1r = -INFINITY, l0 = 0.f, l1 = 0.f;

    const float scale = 0.08838834764831845f;
    int r16 = lane & 15;
    uint32_t cby = (lane >> 4) * 16;
    int qrow0 = qt * 64 + w * 16 + (lane >> 2);

    for (int kt = 0; kt <= qt; kt++) {
        if (kt > 0) __syncthreads();  // done reading previous K/V
#pragma unroll
        for (int i = 0; i < 8; i++) {
            int linear = i * 128 + tid;
            int r = linear >> 4, c = linear & 15;
            size_t go = (size_t)(kt * 64 + r) * HD + c * 8;
            uint32_t dk = sb + SK + r * FROW + c * 16;
            uint32_t dv = sb + SV + r * FROW + c * 16;
            CP_ASYNC16(dk,         (const void*)(Khg + go));
            CP_ASYNC16(dk + FTILE, (const void*)(Klg + go));
            CP_ASYNC16(dv,         (const void*)(Vhg + go));
            CP_ASYNC16(dv + FTILE, (const void*)(Vlg + go));
        }
        CP_COMMIT();
        CP_WAIT0();
        __syncthreads();

        // ---- S = Q K^T (3-term split) ----
        float s[8][4];
#pragma unroll
        for (int t = 0; t < 8; t++)
#pragma unroll
            for (int c = 0; c < 4; c++) s[t][c] = 0.f;
#pragma unroll
        for (int ks = 0; ks < 8; ks++) {
            uint32_t qa = sb + SQ + (w * 16 + r16) * FROW + ks * 32 + cby;
            uint32_t qh[4], ql[4], kh[4][4], kl[4][4];
            LDSM_X4(qh[0], qh[1], qh[2], qh[3], qa);
            LDSM_X4(ql[0], ql[1], ql[2], ql[3], qa + FTILE);
#pragma unroll
            for (int g = 0; g < 4; g++) {
                uint32_t ka = sb + SK + (g * 16 + r16) * FROW + ks * 32 + cby;
                LDSM_X4(kh[g][0], kh[g][1], kh[g][2], kh[g][3], ka);
                LDSM_X4(kl[g][0], kl[g][1], kl[g][2], kl[g][3], ka + FTILE);
            }
#pragma unroll
            for (int t = 0; t < 8; t++) {
                int g = t >> 1, sel = t & 1;
                uint32_t bh0 = kh[g][sel], bh1 = kh[g][sel + 2];
                uint32_t bl0 = kl[g][sel], bl1 = kl[g][sel + 2];
                MMA16816(s[t], qh[0], qh[1], qh[2], qh[3], bh0, bh1);
                MMA16816(s[t], qh[0], qh[1], qh[2], qh[3], bl0, bl1);
                MMA16816(s[t], ql[0], ql[1], ql[2], ql[3], bh0, bh1);
            }
        }

        // ---- softmax (online) ----
        bool diag = (kt == qt);
        float mx0 = -INFINITY, mx1 = -INFINITY;
#pragma unroll
        for (int t = 0; t < 8; t++) {
            int colb = kt * 64 + t * 8 + (lane & 3) * 2;
            s[t][0] *= scale; s[t][1] *= scale; s[t][2] *= scale; s[t][3] *= scale;
            if (diag) {
                if (colb     > qrow0)     s[t][0] = -INFINITY;
                if (colb + 1 > qrow0)     s[t][1] = -INFINITY;
                if (colb     > qrow0 + 8) s[t][2] = -INFINITY;
                if (colb + 1 > qrow0 + 8) s[t][3] = -INFINITY;
            }
            mx0 = fmaxf(mx0, fmaxf(s[t][0], s[t][1]));
            mx1 = fmaxf(mx1, fmaxf(s[t][2], s[t][3]));
        }
        mx0 = fmaxf(mx0, __shfl_xor_sync(0xffffffffu, mx0, 1));
        mx0 = fmaxf(mx0, __shfl_xor_sync(0xffffffffu, mx0, 2));
        mx1 = fmaxf(mx1, __shfl_xor_sync(0xffffffffu, mx1, 1));
        mx1 = fmaxf(mx1, __shfl_xor_sync(0xffffffffu, mx1, 2));
        float mn0 = fmaxf(m0r, mx0), mn1 = fmaxf(m1r, mx1);
        float corr0 = __expf(m0r - mn0), corr1 = __expf(m1r - mn1);
        m0r = mn0; m1r = mn1;

        float sum0 = 0.f, sum1 = 0.f;
        uint32_t ph[4][4], pl[4][4];
#pragma unroll
        for (int t = 0; t < 8; t++) {
            float p0 = __expf(s[t][0] - mn0);
            float p1 = __expf(s[t][1] - mn0);
            float p2 = __expf(s[t][2] - mn1);
            float p3 = __expf(s[t][3] - mn1);
            sum0 += p0 + p1;
            sum1 += p2 + p3;
            float h0 = __bfloat162float(__float2bfloat16(p0));
            float h1 = __bfloat162float(__float2bfloat16(p1));
            float h2 = __bfloat162float(__float2bfloat16(p2));
            float h3 = __bfloat162float(__float2bfloat16(p3));
            int j = t >> 1;
            if ((t & 1) == 0) {
                ph[j][0] = pack_bf16(h0, h1);
                ph[j][1] = pack_bf16(h2, h3);
                pl[j][0] = pack_bf16(p0 - h0, p1 - h1);
                pl[j][1] = pack_bf16(p2 - h2, p3 - h3);
            } else {
                ph[j][2] = pack_bf16(h0, h1);
                ph[j][3] = pack_bf16(h2, h3);
                pl[j][2] = pack_bf16(p0 - h0, p1 - h1);
                pl[j][3] = pack_bf16(p2 - h2, p3 - h3);
            }
        }
        sum0 += __shfl_xor_sync(0xffffffffu, sum0, 1);
        sum0 += __shfl_xor_sync(0xffffffffu, sum0, 2);
        sum1 += __shfl_xor_sync(0xffffffffu, sum1, 1);
        sum1 += __shfl_xor_sync(0xffffffffu, sum1, 2);
        l0 = l0 * corr0 + sum0;
        l1 = l1 * corr1 + sum1;
#pragma unroll
        for (int t = 0; t < 16; t++) {
            o[t][0] *= corr0; o[t][1] *= corr0;
            o[t][2] *= corr1; o[t][3] *= corr1;
        }

        // ---- O += P V (3-term split) ----
#pragma unroll
        for (int j = 0; j < 4; j++) {
#pragma unroll
            for (int g = 0; g < 8; g++) {
                uint32_t va = sb + SV + (j * 16 + r16) * FROW + g * 32 + cby;
                uint32_t vh[4], vl[4];
                LDSM_X4_T(vh[0], vh[1], vh[2], vh[3], va);
                LDSM_X4_T(vl[0], vl[1], vl[2], vl[3], va + FTILE);
                // trans pairs: tile 2g -> {r0,r1}, tile 2g+1 -> {r2,r3}
                MMA16816(o[2 * g],     ph[j][0], ph[j][1], ph[j][2], ph[j][3], vh[0], vh[1]);
                MMA16816(o[2 * g],     ph[j][0], ph[j][1], ph[j][2], ph[j][3], vl[0], vl[1]);
                MMA16816(o[2 * g],     pl[j][0], pl[j][1], pl[j][2], pl[j][3], vh[0], vh[1]);
                MMA16816(o[2 * g + 1], ph[j][0], ph[j][1], ph[j][2], ph[j][3], vh[2], vh[3]);
                MMA16816(o[2 * g + 1], ph[j][0], ph[j][1], ph[j][2], ph[j][3], vl[2], vl[3]);
                MMA16816(o[2 * g + 1], pl[j][0], pl[j][1], pl[j][2], pl[j][3], vh[2], vh[3]);
            }
        }
    }

    // ---- normalize + write y split (bf16 hi/lo) ----
    float inv0 = 1.0f / l0, inv1 = 1.0f / l1;
    int grow0 = b * NT + qt * 64 + w * 16 + (lane >> 2);
#pragma unroll
    for (int t = 0; t < 16; t++) {
        int col = h * 128 + t * 8 + (lane & 3) * 2;
        float v0 = o[t][0] * inv0, v1 = o[t][1] * inv0;
        float v2 = o[t][2] * inv1, v3 = o[t][3] * inv1;
        float h0 = __bfloat162float(__float2bfloat16(v0));
        float h1 = __bfloat162float(__float2bfloat16(v1));
        float h2 = __bfloat162float(__float2bfloat16(v2));
        float h3 = __bfloat162float(__float2bfloat16(v3));
        size_t i0 = (size_t)grow0 * ND + col;
        size_t i1 = (size_t)(grow0 + 8) * ND + col;
        *(uint32_t*)&g_yh[i0] = pack_bf16(h0, h1);
        *(uint32_t*)&g_yl[i0] = pack_bf16(v0 - h0, v1 - h1);
        *(uint32_t*)&g_yh[i1] = pack_bf16(h2, h3);
        *(uint32_t*)&g_yl[i1] = pack_bf16(v2 - h2, v3 - h3);
    }
}

// ---------------- launch ------------------------------------------------------
extern "C" void kernel_launch(void* const* d_in, const int* in_sizes, int n_in,
                              void* d_out, int out_size) {
    const float* x   = (const float*)d_in[0];
    const float* wq  = (const float*)d_in[1];
    const float* wk  = (const float*)d_in[2];
    const float* wv  = (const float*)d_in[3];
    const float* wo  = (const float*)d_in[4];
    const float* qnw = (const float*)d_in[5];
    const float* knw = (const float*)d_in[6];
    float* out = (float*)d_out;

    cudaFuncSetAttribute(flash_kernel, cudaFuncAttributeMaxDynamicSharedMemorySize,
                         FLASH_SMEM);
    cudaFuncSetAttribute(gemm_mma_kernel, cudaFuncAttributeMaxDynamicSharedMemorySize,
                         GEMM_SMEM);

    rope_table_kernel<<<NT, 64>>>();

    split_kernel<<<(NB * NT * ND) / 1024, 256>>>(x, 0, 0, NB * NT * ND);
    split_kernel<<<(2048 * 2048) / 1024, 256>>>(wq, 1, 0, 2048 * 2048);
    split_kernel<<<(512 * 2048) / 1024, 256>>>(wk, 1, (size_t)2048 * 2048, 512 * 2048);
    split_kernel<<<(512 * 2048) / 1024, 256>>>(wv, 1, (size_t)2560 * 2048, 512 * 2048);
    split_kernel<<<(2048 * 2048) / 1024, 256>>>(wo, 2, 0, 2048 * 2048);

    gemm_mma_kernel<<<dim3(32, 24), 256, GEMM_SMEM>>>(0, nullptr);
    rope_norm_kernel<<<dim3(NB * NT, 24), 128>>>(qnw, knw);
    flash_kernel<<<dim3(NT / 64, NH, NB), 128, FLASH_SMEM>>>();
    gemm_mma_kernel<<<dim3(32, 16), 256, GEMM_SMEM>>>(1, out);
}

// round 4
// speedup vs baseline: 2.5256x; 1.0912x over previous
#include <cuda_runtime.h>
#include <cuda_fp16.h>
#include <math.h>
#include <cstdint>

#define NB 2
#define NT 2048
#define ND 2048
#define NH 16
#define NKV 4
#define HD 128

typedef __half f16;

// ---------------- scratch -----------------------------------------------------
static __device__ float g_qkv[(size_t)NB * NT * 3072];
static __device__ float g_cos[NT * 64];
static __device__ float g_sin[NT * 64];
static __device__ f16 g_xh[(size_t)NB * NT * ND], g_xl[(size_t)NB * NT * ND];
static __device__ f16 g_wh[(size_t)3072 * 2048], g_wl[(size_t)3072 * 2048];
static __device__ f16 g_woh[(size_t)2048 * 2048];
static __device__ f16 g_yh[(size_t)NB * NT * ND], g_yl[(size_t)NB * NT * ND];
static __device__ f16 g_Qh[(size_t)NB * NH * NT * HD], g_Ql[(size_t)NB * NH * NT * HD];
static __device__ f16 g_Kh[(size_t)NB * NKV * NT * HD], g_Kl[(size_t)NB * NKV * NT * HD];
static __device__ f16 g_Vh[(size_t)NB * NKV * NT * HD];

// ---------------- PTX helpers (sm_80-compatible) ------------------------------
__device__ __forceinline__ uint32_t smem_u32(const void* p) {
    uint32_t a;
    asm("{ .reg .u64 t; cvta.to.shared.u64 t, %1; cvt.u32.u64 %0, t; }" : "=r"(a) : "l"(p));
    return a;
}
#define CP_ASYNC16(dst, src)                                                   \
    asm volatile("cp.async.cg.shared.global [%0], [%1], 16;"                   \
                 :: "r"(dst), "l"(src) : "memory")
#define CP_COMMIT() asm volatile("cp.async.commit_group;" ::: "memory")
#define CP_WAIT0()  asm volatile("cp.async.wait_group 0;" ::: "memory")
#define CP_WAIT1()  asm volatile("cp.async.wait_group 1;" ::: "memory")
#define LDSM_X4(r0, r1, r2, r3, addr)                                          \
    asm volatile("ldmatrix.sync.aligned.m8n8.x4.shared.b16 {%0,%1,%2,%3}, [%4];" \
                 : "=r"(r0), "=r"(r1), "=r"(r2), "=r"(r3) : "r"(addr))
#define LDSM_X4_T(r0, r1, r2, r3, addr)                                        \
    asm volatile("ldmatrix.sync.aligned.m8n8.x4.trans.shared.b16 {%0,%1,%2,%3}, [%4];" \
                 : "=r"(r0), "=r"(r1), "=r"(r2), "=r"(r3) : "r"(addr))
#define MMA16816(d, a0, a1, a2, a3, b0, b1)                                    \
    asm volatile("mma.sync.aligned.m16n8k16.row.col.f32.f16.f16.f32 "          \
                 "{%0,%1,%2,%3}, {%4,%5,%6,%7}, {%8,%9}, {%0,%1,%2,%3};"       \
                 : "+f"((d)[0]), "+f"((d)[1]), "+f"((d)[2]), "+f"((d)[3])      \
                 : "r"(a0), "r"(a1), "r"(a2), "r"(a3), "r"(b0), "r"(b1))

__device__ __forceinline__ uint32_t pack_f16(float a, float b) {
    __half2 t = __floats2half2_rn(a, b);
    return *(uint32_t*)&t;
}

// ---------------- RoPE table --------------------------------------------------
__global__ void rope_table_kernel() {
    int t = blockIdx.x;
    int i = threadIdx.x;  // 0..63
    double f = exp(-((double)(2 * i) / 128.0) * log(10000.0));
    double a = (double)t * f;
    g_cos[t * 64 + i] = (float)cos(a);
    g_sin[t * 64 + i] = (float)sin(a);
}

// ---------------- fused fp32 -> fp16 hi/lo split (x, wq, wk, wv, wo) ----------
__global__ __launch_bounds__(256) void prep_kernel(const float* __restrict__ x,
                                                   const float* __restrict__ wq,
                                                   const float* __restrict__ wk,
                                                   const float* __restrict__ wv,
                                                   const float* __restrict__ wo) {
    size_t i = ((size_t)blockIdx.x * 256 + threadIdx.x) * 4;
    const float* src;
    f16 *H, *L;
    if (i < 8388608)        { src = x  + i;              H = g_xh + i;               L = g_xl + i; }
    else if (i < 12582912)  { size_t o = i - 8388608;    src = wq + o; H = g_wh + o; L = g_wl + o; }
    else if (i < 13631488)  { size_t o = i - 12582912;   src = wk + o;
                              H = g_wh + 4194304 + o;    L = g_wl + 4194304 + o; }
    else if (i < 14680064)  { size_t o = i - 13631488;   src = wv + o;
                              H = g_wh + 5242880 + o;    L = g_wl + 5242880 + o; }
    else                    { size_t o = i - 14680064;   src = wo + o; H = g_woh + o; L = nullptr; }

    float4 v = *(const float4*)src;
    float vv[4] = {v.x, v.y, v.z, v.w};
    f16 hv[4], lv[4];
#pragma unroll
    for (int e = 0; e < 4; e++) {
        hv[e] = __float2half_rn(vv[e]);
        lv[e] = __float2half_rn(vv[e] - __half2float(hv[e]));
    }
    *(__half2*)(H)     = __halves2half2(hv[0], hv[1]);
    *(__half2*)(H + 2) = __halves2half2(hv[2], hv[3]);
    if (L) {
        *(__half2*)(L)     = __halves2half2(lv[0], lv[1]);
        *(__half2*)(L + 2) = __halves2half2(lv[2], lv[3]);
    }
}

// ---------------- split-fp16 GEMM via mma.sync --------------------------------
// NTERMS=3: C = AhBh + AhBl + AlBh (QKV). NTERMS=2: C = AhBh + AlBh (WO, B hi only).
// CTA tile 128x128, K-chunk 32, 3-stage cp.async pipeline.
// smem per buffer: Ah,Al,Bh,(Bl) each [128][40] f16 -> 40960B; 3 buffers.
#define GEMM_SMEM (3 * 40960)

template <int NTERMS>
__global__ __launch_bounds__(256) void gemm_mma_kernel(float* __restrict__ Cout) {
    extern __shared__ char smem[];
    const f16 *Ah, *Al, *Bh, *Bl;
    float* C;
    int ldc;
    if (NTERMS == 3) { Ah = g_xh; Al = g_xl; Bh = g_wh;  Bl = g_wl; C = g_qkv; ldc = 3072; }
    else             { Ah = g_yh; Al = g_yl; Bh = g_woh; Bl = nullptr; C = Cout; ldc = 2048; }
    uint32_t sb = smem_u32(smem);
    int tid = threadIdx.x, lane = tid & 31, wid = tid >> 5;
    int wm = wid >> 1, wn = wid & 1;
    int m0 = blockIdx.x * 128, n0 = blockIdx.y * 128;

    int row = tid >> 1, half = tid & 1;
    size_t aoff0 = (size_t)(m0 + row) * 2048 + half * 16;
    size_t boff0 = (size_t)(n0 + row) * 2048 + half * 16;
    uint32_t dst0 = sb + row * 80 + half * 32;

    float acc[2][8][4];
#pragma unroll
    for (int mi = 0; mi < 2; mi++)
#pragma unroll
        for (int t = 0; t < 8; t++)
#pragma unroll
            for (int c = 0; c < 4; c++) acc[mi][t][c] = 0.f;

#define GEMM_PREFETCH(c, bsel) do {                                            \
    uint32_t d = dst0 + (bsel) * 40960;                                        \
    size_t ao = aoff0 + (size_t)(c) * 32, bo = boff0 + (size_t)(c) * 32;       \
    CP_ASYNC16(d,         (const void*)(Ah + ao));                             \
    CP_ASYNC16(d + 16,    (const void*)(Ah + ao + 8));                         \
    CP_ASYNC16(d + 10240, (const void*)(Al + ao));                             \
    CP_ASYNC16(d + 10256, (const void*)(Al + ao + 8));                         \
    CP_ASYNC16(d + 20480, (const void*)(Bh + bo));                             \
    CP_ASYNC16(d + 20496, (const void*)(Bh + bo + 8));                         \
    if (NTERMS == 3) {                                                         \
        CP_ASYNC16(d + 30720, (const void*)(Bl + bo));                         \
        CP_ASYNC16(d + 30736, (const void*)(Bl + bo + 8));                     \
    }                                                                          \
} while (0)

    GEMM_PREFETCH(0, 0);
    CP_COMMIT();
    GEMM_PREFETCH(1, 1);
    CP_COMMIT();

    int r16 = lane & 15;
    uint32_t cby = (lane >> 4) * 16;

    for (int c = 0; c < 64; c++) {
        CP_WAIT1();
        __syncthreads();
        if (c < 62) { GEMM_PREFETCH(c + 2, (c + 2) % 3); CP_COMMIT(); }
        uint32_t base = sb + (c % 3) * 40960;
#pragma unroll
        for (int ks = 0; ks < 2; ks++) {
            uint32_t ahf[2][4], alf[2][4], bhf[4][4], blf[4][4];
#pragma unroll
            for (int mi = 0; mi < 2; mi++) {
                uint32_t ad = base + ((wm * 32 + mi * 16 + r16) * 40 + ks * 16) * 2 + cby;
                LDSM_X4(ahf[mi][0], ahf[mi][1], ahf[mi][2], ahf[mi][3], ad);
                LDSM_X4(alf[mi][0], alf[mi][1], alf[mi][2], alf[mi][3], ad + 10240);
            }
#pragma unroll
            for (int g = 0; g < 4; g++) {
                uint32_t bd = base + 20480 + ((wn * 64 + g * 16 + r16) * 40 + ks * 16) * 2 + cby;
                LDSM_X4(bhf[g][0], bhf[g][1], bhf[g][2], bhf[g][3], bd);
                if (NTERMS == 3)
                    LDSM_X4(blf[g][0], blf[g][1], blf[g][2], blf[g][3], bd + 10240);
            }
#pragma unroll
            for (int mi = 0; mi < 2; mi++)
#pragma unroll
                for (int t = 0; t < 8; t++) {
                    int g = t >> 1, s = t & 1;
                    uint32_t bh0 = bhf[g][s], bh1 = bhf[g][s + 2];
                    MMA16816(acc[mi][t], ahf[mi][0], ahf[mi][1], ahf[mi][2], ahf[mi][3], bh0, bh1);
                    MMA16816(acc[mi][t], alf[mi][0], alf[mi][1], alf[mi][2], alf[mi][3], bh0, bh1);
                    if (NTERMS == 3) {
                        uint32_t bl0 = blf[g][s], bl1 = blf[g][s + 2];
                        MMA16816(acc[mi][t], ahf[mi][0], ahf[mi][1], ahf[mi][2], ahf[mi][3], bl0, bl1);
                    }
                }
        }
        __syncthreads();
    }

#pragma unroll
    for (int mi = 0; mi < 2; mi++)
#pragma unroll
        for (int t = 0; t < 8; t++) {
            int r = m0 + wm * 32 + mi * 16 + (lane >> 2);
            int cc = n0 + wn * 64 + t * 8 + (lane & 3) * 2;
            *(float2*)&C[(size_t)r * ldc + cc]       = make_float2(acc[mi][t][0], acc[mi][t][1]);
            *(float2*)&C[(size_t)(r + 8) * ldc + cc] = make_float2(acc[mi][t][2], acc[mi][t][3]);
        }
}

// ---------------- RoPE + RMSNorm + transpose + split -------------------------
__global__ __launch_bounds__(128) void rope_norm_kernel(const float* __restrict__ qnw,
                                                        const float* __restrict__ knw) {
    int m = blockIdx.x;
    int r = blockIdx.y;
    int d = threadIdx.x;
    int t = m & (NT - 1);
    int b = m >> 11;
    const float* base = g_qkv + (size_t)m * 3072;

    if (r >= 20) {  // V: fp16 hi only
        int kv = r - 20;
        size_t idx = (((size_t)(b * NKV + kv)) * NT + t) * HD + d;
        g_Vh[idx] = __float2half_rn(base[2560 + kv * 128 + d]);
        return;
    }
    float x, w;
    f16 *dh, *dl;
    size_t idx;
    if (r < 16) {
        x = base[r * 128 + d];
        w = qnw[d];
        idx = (((size_t)(b * NH + r)) * NT + t) * HD + d;
        dh = g_Qh; dl = g_Ql;
    } else {
        int kv = r - 16;
        x = base[2048 + kv * 128 + d];
        w = knw[d];
        idx = (((size_t)(b * NKV + kv)) * NT + t) * HD + d;
        dh = g_Kh; dl = g_Kl;
    }
    int i = d >> 1;
    float c = g_cos[t * 64 + i];
    float s = g_sin[t * 64 + i];
    float part = __shfl_xor_sync(0xffffffffu, x, 1);
    float o = (d & 1) ? fmaf(part, s, x * c) : fmaf(x, c, -part * s);

    __shared__ float red[4];
    float sq = o * o;
#pragma unroll
    for (int off = 16; off >= 1; off >>= 1) sq += __shfl_xor_sync(0xffffffffu, sq, off);
    if ((d & 31) == 0) red[d >> 5] = sq;
    __syncthreads();
    float var = (red[0] + red[1] + red[2] + red[3]) * (1.0f / 128.0f);
    float out = o * rsqrtf(var + 1.1920929e-7f) * w;
    f16 h = __float2half_rn(out);
    dh[idx] = h;
    dl[idx] = __float2half_rn(out - __half2float(h));
}

// ---------------- flash attention via mma.sync (split fp16) ------------------
// 128 thr = 4 warps, BQ=64, BK=64, hd=128.
// smem: Qh,Ql,Kh,Kl,Vh each [64][136] f16 (272B rows) = 5 tiles.
#define FROW 272
#define FTILE (64 * FROW)
#define FLASH_SMEM (5 * FTILE)

__global__ __launch_bounds__(128, 2) void flash_kernel() {
    extern __shared__ char smem[];
    uint32_t sb = smem_u32(smem);
    const uint32_t SQ = 0, SK = 2 * FTILE, SV = 4 * FTILE;

    int qt = blockIdx.x, h = blockIdx.y, b = blockIdx.z;
    int kvh = h >> 2;
    int tid = threadIdx.x, lane = tid & 31, w = tid >> 5;

    const f16* Qhg = g_Qh + ((size_t)(b * NH + h) * NT + qt * 64) * HD;
    const f16* Qlg = g_Ql + ((size_t)(b * NH + h) * NT + qt * 64) * HD;
    const f16* Khg = g_Kh + (size_t)(b * NKV + kvh) * NT * HD;
    const f16* Klg = g_Kl + (size_t)(b * NKV + kvh) * NT * HD;
    const f16* Vhg = g_Vh + (size_t)(b * NKV + kvh) * NT * HD;

    // Q (group 0)
#pragma unroll
    for (int i = 0; i < 8; i++) {
        int linear = i * 128 + tid;
        int r = linear >> 4, c = linear & 15;
        uint32_t d = sb + SQ + r * FROW + c * 16;
        CP_ASYNC16(d,         (const void*)(Qhg + r * HD + c * 8));
        CP_ASYNC16(d + FTILE, (const void*)(Qlg + r * HD + c * 8));
    }
    CP_COMMIT();

    float o[16][4];
#pragma unroll
    for (int t = 0; t < 16; t++)
#pragma unroll
        for (int c = 0; c < 4; c++) o[t][c] = 0.f;
    float m0r = -INFINITY, m1r = -INFINITY, l0 = 0.f, l1 = 0.f;

    const float scale = 0.08838834764831845f;
    int r16 = lane & 15;
    uint32_t cby = (lane >> 4) * 16;
    int qrow0 = qt * 64 + w * 16 + (lane >> 2);

    for (int kt = 0; kt <= qt; kt++) {
        if (kt > 0) __syncthreads();  // all warps done with previous K/V smem
        // K group
#pragma unroll
        for (int i = 0; i < 8; i++) {
            int linear = i * 128 + tid;
            int r = linear >> 4, c = linear & 15;
            size_t go = (size_t)(kt * 64 + r) * HD + c * 8;
            uint32_t dk = sb + SK + r * FROW + c * 16;
            CP_ASYNC16(dk,         (const void*)(Khg + go));
            CP_ASYNC16(dk + FTILE, (const void*)(Klg + go));
        }
        CP_COMMIT();
        // V group
#pragma unroll
        for (int i = 0; i < 8; i++) {
            int linear = i * 128 + tid;
            int r = linear >> 4, c = linear & 15;
            size_t go = (size_t)(kt * 64 + r) * HD + c * 8;
            CP_ASYNC16(sb + SV + r * FROW + c * 16, (const void*)(Vhg + go));
        }
        CP_COMMIT();
        CP_WAIT1();          // K (and Q) landed; V still in flight
        __syncthreads();

        // ---- S = Q K^T (3-term fp16 split) ----
        float s[8][4];
#pragma unroll
        for (int t = 0; t < 8; t++)
#pragma unroll
            for (int c = 0; c < 4; c++) s[t][c] = 0.f;
#pragma unroll
        for (int ks = 0; ks < 8; ks++) {
            uint32_t qa = sb + SQ + (w * 16 + r16) * FROW + ks * 32 + cby;
            uint32_t qh[4], ql[4], kh[4][4], kl[4][4];
            LDSM_X4(qh[0], qh[1], qh[2], qh[3], qa);
            LDSM_X4(ql[0], ql[1], ql[2], ql[3], qa + FTILE);
#pragma unroll
            for (int g = 0; g < 4; g++) {
                uint32_t ka = sb + SK + (g * 16 + r16) * FROW + ks * 32 + cby;
                LDSM_X4(kh[g][0], kh[g][1], kh[g][2], kh[g][3], ka);
                LDSM_X4(kl[g][0], kl[g][1], kl[g][2], kl[g][3], ka + FTILE);
            }
#pragma unroll
            for (int t = 0; t < 8; t++) {
                int g = t >> 1, sel = t & 1;
                uint32_t bh0 = kh[g][sel], bh1 = kh[g][sel + 2];
                uint32_t bl0 = kl[g][sel], bl1 = kl[g][sel + 2];
                MMA16816(s[t], qh[0], qh[1], qh[2], qh[3], bh0, bh1);
                MMA16816(s[t], qh[0], qh[1], qh[2], qh[3], bl0, bl1);
                MMA16816(s[t], ql[0], ql[1], ql[2], ql[3], bh0, bh1);
            }
        }

        // ---- online softmax ----
        bool diag = (kt == qt);
        float mx0 = -INFINITY, mx1 = -INFINITY;
#pragma unroll
        for (int t = 0; t < 8; t++) {
            int colb = kt * 64 + t * 8 + (lane & 3) * 2;
            s[t][0] *= scale; s[t][1] *= scale; s[t][2] *= scale; s[t][3] *= scale;
            if (diag) {
                if (colb     > qrow0)     s[t][0] = -INFINITY;
                if (colb + 1 > qrow0)     s[t][1] = -INFINITY;
                if (colb     > qrow0 + 8) s[t][2] = -INFINITY;
                if (colb + 1 > qrow0 + 8) s[t][3] = -INFINITY;
            }
            mx0 = fmaxf(mx0, fmaxf(s[t][0], s[t][1]));
            mx1 = fmaxf(mx1, fmaxf(s[t][2], s[t][3]));
        }
        mx0 = fmaxf(mx0, __shfl_xor_sync(0xffffffffu, mx0, 1));
        mx0 = fmaxf(mx0, __shfl_xor_sync(0xffffffffu, mx0, 2));
        mx1 = fmaxf(mx1, __shfl_xor_sync(0xffffffffu, mx1, 1));
        mx1 = fmaxf(mx1, __shfl_xor_sync(0xffffffffu, mx1, 2));
        float mn0 = fmaxf(m0r, mx0), mn1 = fmaxf(m1r, mx1);
        float corr0 = __expf(m0r - mn0), corr1 = __expf(m1r - mn1);
        m0r = mn0; m1r = mn1;

        float sum0 = 0.f, sum1 = 0.f;
        uint32_t ph[4][4], pl[4][4];
#pragma unroll
        for (int t = 0; t < 8; t++) {
            float p0 = __expf(s[t][0] - mn0);
            float p1 = __expf(s[t][1] - mn0);
            float p2 = __expf(s[t][2] - mn1);
            float p3 = __expf(s[t][3] - mn1);
            sum0 += p0 + p1;
            sum1 += p2 + p3;
            float h0 = __half2float(__float2half_rn(p0));
            float h1 = __half2float(__float2half_rn(p1));
            float h2 = __half2float(__float2half_rn(p2));
            float h3 = __half2float(__float2half_rn(p3));
            int j = t >> 1;
            if ((t & 1) == 0) {
                ph[j][0] = pack_f16(h0, h1);
                ph[j][1] = pack_f16(h2, h3);
                pl[j][0] = pack_f16(p0 - h0, p1 - h1);
                pl[j][1] = pack_f16(p2 - h2, p3 - h3);
            } else {
                ph[j][2] = pack_f16(h0, h1);
                ph[j][3] = pack_f16(h2, h3);
                pl[j][2] = pack_f16(p0 - h0, p1 - h1);
                pl[j][3] = pack_f16(p2 - h2, p3 - h3);
            }
        }
        sum0 += __shfl_xor_sync(0xffffffffu, sum0, 1);
        sum0 += __shfl_xor_sync(0xffffffffu, sum0, 2);
        sum1 += __shfl_xor_sync(0xffffffffu, sum1, 1);
        sum1 += __shfl_xor_sync(0xffffffffu, sum1, 2);
        l0 = l0 * corr0 + sum0;
        l1 = l1 * corr1 + sum1;
#pragma unroll
        for (int t = 0; t < 16; t++) {
            o[t][0] *= corr0; o[t][1] *= corr0;
            o[t][2] *= corr1; o[t][3] *= corr1;
        }

        CP_WAIT0();          // V landed
        __syncthreads();

        // ---- O += P V (2-term: Ph Vh + Pl Vh) ----
#pragma unroll
        for (int j = 0; j < 4; j++) {
#pragma unroll
            for (int g = 0; g < 8; g++) {
                uint32_t va = sb + SV + (j * 16 + r16) * FROW + g * 32 + cby;
                uint32_t vh[4];
                LDSM_X4_T(vh[0], vh[1], vh[2], vh[3], va);
                MMA16816(o[2 * g],     ph[j][0], ph[j][1], ph[j][2], ph[j][3], vh[0], vh[1]);
                MMA16816(o[2 * g],     pl[j][0], pl[j][1], pl[j][2], pl[j][3], vh[0], vh[1]);
                MMA16816(o[2 * g + 1], ph[j][0], ph[j][1], ph[j][2], ph[j][3], vh[2], vh[3]);
                MMA16816(o[2 * g + 1], pl[j][0], pl[j][1], pl[j][2], pl[j][3], vh[2], vh[3]);
            }
        }
    }

    // ---- normalize + write y split (fp16 hi/lo) ----
    float inv0 = 1.0f / l0, inv1 = 1.0f / l1;
    int grow0 = b * NT + qt * 64 + w * 16 + (lane >> 2);
#pragma unroll
    for (int t = 0; t < 16; t++) {
        int col = h * 128 + t * 8 + (lane & 3) * 2;
        float v0 = o[t][0] * inv0, v1 = o[t][1] * inv0;
        float v2 = o[t][2] * inv1, v3 = o[t][3] * inv1;
        float h0 = __half2float(__float2half_rn(v0));
        float h1 = __half2float(__float2half_rn(v1));
        float h2 = __half2float(__float2half_rn(v2));
        float h3 = __half2float(__float2half_rn(v3));
        size_t i0 = (size_t)grow0 * ND + col;
        size_t i1 = (size_t)(grow0 + 8) * ND + col;
        *(uint32_t*)&g_yh[i0] = pack_f16(h0, h1);
        *(uint32_t*)&g_yl[i0] = pack_f16(v0 - h0, v1 - h1);
        *(uint32_t*)&g_yh[i1] = pack_f16(h2, h3);
        *(uint32_t*)&g_yl[i1] = pack_f16(v2 - h2, v3 - h3);
    }
}

// ---------------- launch ------------------------------------------------------
extern "C" void kernel_launch(void* const* d_in, const int* in_sizes, int n_in,
                              void* d_out, int out_size) {
    const float* x   = (const float*)d_in[0];
    const float* wq  = (const float*)d_in[1];
    const float* wk  = (const float*)d_in[2];
    const float* wv  = (const float*)d_in[3];
    const float* wo  = (const float*)d_in[4];
    const float* qnw = (const float*)d_in[5];
    const float* knw = (const float*)d_in[6];
    float* out = (float*)d_out;

    cudaFuncSetAttribute(flash_kernel, cudaFuncAttributeMaxDynamicSharedMemorySize,
                         FLASH_SMEM);
    cudaFuncSetAttribute(gemm_mma_kernel<3>, cudaFuncAttributeMaxDynamicSharedMemorySize,
                         GEMM_SMEM);
    cudaFuncSetAttribute(gemm_mma_kernel<2>, cudaFuncAttributeMaxDynamicSharedMemorySize,
                         GEMM_SMEM);

    rope_table_kernel<<<NT, 64>>>();
    prep_kernel<<<18432, 256>>>(x, wq, wk, wv, wo);
    gemm_mma_kernel<3><<<dim3(32, 24), 256, GEMM_SMEM>>>(nullptr);
    rope_norm_kernel<<<dim3(NB * NT, 24), 128>>>(qnw, knw);
    flash_kernel<<<dim3(NT / 64, NH, NB), 128, FLASH_SMEM>>>();
    gemm_mma_kernel<2><<<dim3(32, 16), 256, GEMM_SMEM>>>(out);
}

// round 5
// speedup vs baseline: 3.4304x; 1.3582x over previous
#include <cuda_runtime.h>
#include <cuda_fp16.h>
#include <math.h>
#include <cstdint>

#define NB 2
#define NT 2048
#define ND 2048
#define NH 16
#define NKV 4
#define HD 128

typedef __half f16;

// ---------------- scratch -----------------------------------------------------
static __device__ float g_qkv[(size_t)NB * NT * 3072];
static __device__ float g_cos[NT * 64];
static __device__ float g_sin[NT * 64];
static __device__ f16 g_xh[(size_t)NB * NT * ND], g_xl[(size_t)NB * NT * ND];
static __device__ f16 g_wh[(size_t)3072 * 2048];          // [wq;wk;wv] hi
static __device__ f16 g_woh[(size_t)2048 * 2048];
static __device__ f16 g_yh[(size_t)NB * NT * ND], g_yl[(size_t)NB * NT * ND];
static __device__ f16 g_Qh[(size_t)NB * NH * NT * HD], g_Ql[(size_t)NB * NH * NT * HD];
static __device__ f16 g_Kh[(size_t)NB * NKV * NT * HD];
static __device__ f16 g_Vh[(size_t)NB * NKV * NT * HD];

// ---------------- PTX helpers (sm_80-compatible) ------------------------------
__device__ __forceinline__ uint32_t smem_u32(const void* p) {
    uint32_t a;
    asm("{ .reg .u64 t; cvta.to.shared.u64 t, %1; cvt.u32.u64 %0, t; }" : "=r"(a) : "l"(p));
    return a;
}
#define CP_ASYNC16(dst, src)                                                   \
    asm volatile("cp.async.cg.shared.global [%0], [%1], 16;"                   \
                 :: "r"(dst), "l"(src) : "memory")
#define CP_COMMIT() asm volatile("cp.async.commit_group;" ::: "memory")
#define CP_WAIT0()  asm volatile("cp.async.wait_group 0;" ::: "memory")
#define CP_WAIT1()  asm volatile("cp.async.wait_group 1;" ::: "memory")
#define LDSM_X4(r0, r1, r2, r3, addr)                                          \
    asm volatile("ldmatrix.sync.aligned.m8n8.x4.shared.b16 {%0,%1,%2,%3}, [%4];" \
                 : "=r"(r0), "=r"(r1), "=r"(r2), "=r"(r3) : "r"(addr))
#define LDSM_X4_T(r0, r1, r2, r3, addr)                                        \
    asm volatile("ldmatrix.sync.aligned.m8n8.x4.trans.shared.b16 {%0,%1,%2,%3}, [%4];" \
                 : "=r"(r0), "=r"(r1), "=r"(r2), "=r"(r3) : "r"(addr))
#define MMA16816(d, a0, a1, a2, a3, b0, b1)                                    \
    asm volatile("mma.sync.aligned.m16n8k16.row.col.f32.f16.f16.f32 "          \
                 "{%0,%1,%2,%3}, {%4,%5,%6,%7}, {%8,%9}, {%0,%1,%2,%3};"       \
                 : "+f"((d)[0]), "+f"((d)[1]), "+f"((d)[2]), "+f"((d)[3])      \
                 : "r"(a0), "r"(a1), "r"(a2), "r"(a3), "r"(b0), "r"(b1))

__device__ __forceinline__ uint32_t pack_f16(float a, float b) {
    __half2 t = __floats2half2_rn(a, b);
    return *(uint32_t*)&t;
}

// ---------------- RoPE table --------------------------------------------------
__global__ void rope_table_kernel() {
    int t = blockIdx.x;
    int i = threadIdx.x;  // 0..63
    double f = exp(-((double)(2 * i) / 128.0) * log(10000.0));
    double a = (double)t * f;
    g_cos[t * 64 + i] = (float)cos(a);
    g_sin[t * 64 + i] = (float)sin(a);
}

// ---------------- fused fp32 -> fp16 prep (x split; weights hi-only) ----------
__global__ __launch_bounds__(256) void prep_kernel(const float* __restrict__ x,
                                                   const float* __restrict__ wq,
                                                   const float* __restrict__ wk,
                                                   const float* __restrict__ wv,
                                                   const float* __restrict__ wo) {
    size_t i = ((size_t)blockIdx.x * 256 + threadIdx.x) * 4;
    const float* src;
    f16 *H, *L = nullptr;
    if (i < 8388608)        { src = x  + i;            H = g_xh + i; L = g_xl + i; }
    else if (i < 12582912)  { size_t o = i - 8388608;  src = wq + o; H = g_wh + o; }
    else if (i < 13631488)  { size_t o = i - 12582912; src = wk + o; H = g_wh + 4194304 + o; }
    else if (i < 14680064)  { size_t o = i - 13631488; src = wv + o; H = g_wh + 5242880 + o; }
    else                    { size_t o = i - 14680064; src = wo + o; H = g_woh + o; }

    float4 v = *(const float4*)src;
    float vv[4] = {v.x, v.y, v.z, v.w};
    f16 hv[4];
#pragma unroll
    for (int e = 0; e < 4; e++) hv[e] = __float2half_rn(vv[e]);
    *(__half2*)(H)     = __halves2half2(hv[0], hv[1]);
    *(__half2*)(H + 2) = __halves2half2(hv[2], hv[3]);
    if (L) {
        f16 lv[4];
#pragma unroll
        for (int e = 0; e < 4; e++) lv[e] = __float2half_rn(vv[e] - __half2float(hv[e]));
        *(__half2*)(L)     = __halves2half2(lv[0], lv[1]);
        *(__half2*)(L + 2) = __halves2half2(lv[2], lv[3]);
    }
}

// ---------------- 2-term split-fp16 GEMM: C = (Ah+Al) x Bh^T ------------------
// CTA tile 128x128, K-chunk 32, 3-stage cp.async pipeline.
// smem per buffer: Ah,Al,Bh each [128][40] f16 -> 30720B; 3 buffers.
#define GEMM_SMEM (3 * 30720)

__global__ __launch_bounds__(256) void gemm_mma_kernel(int mode, float* __restrict__ Cout) {
    extern __shared__ char smem[];
    const f16 *Ah, *Al, *Bh;
    float* C;
    int ldc;
    if (mode == 0) { Ah = g_xh; Al = g_xl; Bh = g_wh;  C = g_qkv; ldc = 3072; }
    else           { Ah = g_yh; Al = g_yl; Bh = g_woh; C = Cout;  ldc = 2048; }
    uint32_t sb = smem_u32(smem);
    int tid = threadIdx.x, lane = tid & 31, wid = tid >> 5;
    int wm = wid >> 1, wn = wid & 1;
    int m0 = blockIdx.x * 128, n0 = blockIdx.y * 128;

    int row = tid >> 1, half = tid & 1;
    size_t aoff0 = (size_t)(m0 + row) * 2048 + half * 16;
    size_t boff0 = (size_t)(n0 + row) * 2048 + half * 16;
    uint32_t dst0 = sb + row * 80 + half * 32;

    float acc[2][8][4];
#pragma unroll
    for (int mi = 0; mi < 2; mi++)
#pragma unroll
        for (int t = 0; t < 8; t++)
#pragma unroll
            for (int c = 0; c < 4; c++) acc[mi][t][c] = 0.f;

#define GEMM_PREFETCH(c, bsel) do {                                            \
    uint32_t d = dst0 + (bsel) * 30720;                                        \
    size_t ao = aoff0 + (size_t)(c) * 32, bo = boff0 + (size_t)(c) * 32;       \
    CP_ASYNC16(d,         (const void*)(Ah + ao));                             \
    CP_ASYNC16(d + 16,    (const void*)(Ah + ao + 8));                         \
    CP_ASYNC16(d + 10240, (const void*)(Al + ao));                             \
    CP_ASYNC16(d + 10256, (const void*)(Al + ao + 8));                         \
    CP_ASYNC16(d + 20480, (const void*)(Bh + bo));                             \
    CP_ASYNC16(d + 20496, (const void*)(Bh + bo + 8));                         \
} while (0)

    GEMM_PREFETCH(0, 0);
    CP_COMMIT();
    GEMM_PREFETCH(1, 1);
    CP_COMMIT();

    int r16 = lane & 15;
    uint32_t cby = (lane >> 4) * 16;

    for (int c = 0; c < 64; c++) {
        CP_WAIT1();
        __syncthreads();
        if (c < 62) { GEMM_PREFETCH(c + 2, (c + 2) % 3); CP_COMMIT(); }
        uint32_t base = sb + (c % 3) * 30720;
#pragma unroll
        for (int ks = 0; ks < 2; ks++) {
            uint32_t ahf[2][4], alf[2][4], bhf[4][4];
#pragma unroll
            for (int mi = 0; mi < 2; mi++) {
                uint32_t ad = base + ((wm * 32 + mi * 16 + r16) * 40 + ks * 16) * 2 + cby;
                LDSM_X4(ahf[mi][0], ahf[mi][1], ahf[mi][2], ahf[mi][3], ad);
                LDSM_X4(alf[mi][0], alf[mi][1], alf[mi][2], alf[mi][3], ad + 10240);
            }
#pragma unroll
            for (int g = 0; g < 4; g++) {
                uint32_t bd = base + 20480 + ((wn * 64 + g * 16 + r16) * 40 + ks * 16) * 2 + cby;
                LDSM_X4(bhf[g][0], bhf[g][1], bhf[g][2], bhf[g][3], bd);
            }
#pragma unroll
            for (int mi = 0; mi < 2; mi++)
#pragma unroll
                for (int t = 0; t < 8; t++) {
                    int g = t >> 1, s = t & 1;
                    uint32_t bh0 = bhf[g][s], bh1 = bhf[g][s + 2];
                    MMA16816(acc[mi][t], ahf[mi][0], ahf[mi][1], ahf[mi][2], ahf[mi][3], bh0, bh1);
                    MMA16816(acc[mi][t], alf[mi][0], alf[mi][1], alf[mi][2], alf[mi][3], bh0, bh1);
                }
        }
        __syncthreads();
    }

#pragma unroll
    for (int mi = 0; mi < 2; mi++)
#pragma unroll
        for (int t = 0; t < 8; t++) {
            int r = m0 + wm * 32 + mi * 16 + (lane >> 2);
            int cc = n0 + wn * 64 + t * 8 + (lane & 3) * 2;
            *(float2*)&C[(size_t)r * ldc + cc]       = make_float2(acc[mi][t][0], acc[mi][t][1]);
            *(float2*)&C[(size_t)(r + 8) * ldc + cc] = make_float2(acc[mi][t][2], acc[mi][t][3]);
        }
}

// ---------------- RoPE + RMSNorm + transpose + split (warp per head-row) ------
// grid (NB*NT, 6), block 128 = 4 warps; r = by*4+warp: 0..15 Q, 16..19 K, 20..23 V
__global__ __launch_bounds__(128) void rope_norm_kernel(const float* __restrict__ qnw,
                                                        const float* __restrict__ knw) {
    int m = blockIdx.x;
    int w = threadIdx.x >> 5, lane = threadIdx.x & 31;
    int r = blockIdx.y * 4 + w;
    int t = m & (NT - 1);
    int b = m >> 11;
    const float* base = g_qkv + (size_t)m * 3072;
    int d0 = lane * 4;

    if (r >= 20) {  // V: fp16 hi only
        int kv = r - 20;
        float4 v = *(const float4*)(base + 2560 + kv * 128 + d0);
        size_t idx = (((size_t)(b * NKV + kv)) * NT + t) * HD + d0;
        uint2 pk = make_uint2(pack_f16(v.x, v.y), pack_f16(v.z, v.w));
        *(uint2*)&g_Vh[idx] = pk;
        return;
    }
    float4 xv;
    const float* nw;
    f16 *dh, *dl;
    size_t idx;
    if (r < 16) {
        xv = *(const float4*)(base + r * 128 + d0);
        nw = qnw;
        idx = (((size_t)(b * NH + r)) * NT + t) * HD + d0;
        dh = g_Qh; dl = g_Ql;
    } else {
        int kv = r - 16;
        xv = *(const float4*)(base + 2048 + kv * 128 + d0);
        nw = knw;
        idx = (((size_t)(b * NKV + kv)) * NT + t) * HD + d0;
        dh = g_Kh; dl = nullptr;
    }
    float2 cs0 = *(const float2*)(g_cos + t * 64 + lane * 2);
    float2 sn0 = *(const float2*)(g_sin + t * 64 + lane * 2);
    float o0 = xv.x * cs0.x - xv.y * sn0.x;
    float o1 = xv.x * sn0.x + xv.y * cs0.x;
    float o2 = xv.z * cs0.y - xv.w * sn0.y;
    float o3 = xv.z * sn0.y + xv.w * cs0.y;

    float sq = o0 * o0 + o1 * o1 + o2 * o2 + o3 * o3;
#pragma unroll
    for (int off = 16; off >= 1; off >>= 1) sq += __shfl_xor_sync(0xffffffffu, sq, off);
    float rs = rsqrtf(sq * (1.0f / 128.0f) + 1.1920929e-7f);

    float4 wv = *(const float4*)(nw + d0);
    float v0 = o0 * rs * wv.x, v1 = o1 * rs * wv.y;
    float v2 = o2 * rs * wv.z, v3 = o3 * rs * wv.w;
    f16 h0 = __float2half_rn(v0), h1 = __float2half_rn(v1);
    f16 h2 = __float2half_rn(v2), h3 = __float2half_rn(v3);
    *(uint2*)&dh[idx] = make_uint2(pack_f16(v0, v1), pack_f16(v2, v3));
    if (dl) {
        *(uint2*)&dl[idx] = make_uint2(
            pack_f16(v0 - __half2float(h0), v1 - __half2float(h1)),
            pack_f16(v2 - __half2float(h2), v3 - __half2float(h3)));
    }
}

// ---------------- flash attention via mma.sync (2-term QK, 2-term PV) --------
// 128 thr = 4 warps, BQ=64, BK=64, hd=128.
// smem: Qh,Ql,Kh,Vh each [64][136] f16 (272B rows) = 4 tiles.
#define FROW 272
#define FTILE (64 * FROW)
#define FLASH_SMEM (4 * FTILE)

__global__ __launch_bounds__(128, 2) void flash_kernel() {
    extern __shared__ char smem[];
    uint32_t sb = smem_u32(smem);
    const uint32_t SQ = 0, SK = 2 * FTILE, SV = 3 * FTILE;

    int qt = (int)gridDim.x - 1 - (int)blockIdx.x;  // long rows first
    int h = blockIdx.y, b = blockIdx.z;
    int kvh = h >> 2;
    int tid = threadIdx.x, lane = tid & 31, w = tid >> 5;

    const f16* Qhg = g_Qh + ((size_t)(b * NH + h) * NT + qt * 64) * HD;
    const f16* Qlg = g_Ql + ((size_t)(b * NH + h) * NT + qt * 64) * HD;
    const f16* Khg = g_Kh + (size_t)(b * NKV + kvh) * NT * HD;
    const f16* Vhg = g_Vh + (size_t)(b * NKV + kvh) * NT * HD;

    // Q (group 0)
#pragma unroll
    for (int i = 0; i < 8; i++) {
        int linear = i * 128 + tid;
        int r = linear >> 4, c = linear & 15;
        uint32_t d = sb + SQ + r * FROW + c * 16;
        CP_ASYNC16(d,         (const void*)(Qhg + r * HD + c * 8));
        CP_ASYNC16(d + FTILE, (const void*)(Qlg + r * HD + c * 8));
    }
    CP_COMMIT();

    float o[16][4];
#pragma unroll
    for (int t = 0; t < 16; t++)
#pragma unroll
        for (int c = 0; c < 4; c++) o[t][c] = 0.f;
    float m0r = -INFINITY, m1r = -INFINITY, l0 = 0.f, l1 = 0.f;

    const float scale = 0.08838834764831845f;
    int r16 = lane & 15;
    uint32_t cby = (lane >> 4) * 16;
    int qrow0 = qt * 64 + w * 16 + (lane >> 2);

    for (int kt = 0; kt <= qt; kt++) {
        if (kt > 0) __syncthreads();
        // K group
#pragma unroll
        for (int i = 0; i < 4; i++) {
            int linear = i * 128 + tid;
            int r = linear >> 3, c = linear & 7;
            size_t go = (size_t)(kt * 64 + r) * HD + c * 16;
            CP_ASYNC16(sb + SK + r * FROW + c * 32, (const void*)(Khg + go));
            CP_ASYNC16(sb + SK + r * FROW + c * 32 + 16, (const void*)(Khg + go + 8));
        }
        CP_COMMIT();
        // V group
#pragma unroll
        for (int i = 0; i < 4; i++) {
            int linear = i * 128 + tid;
            int r = linear >> 3, c = linear & 7;
            size_t go = (size_t)(kt * 64 + r) * HD + c * 16;
            CP_ASYNC16(sb + SV + r * FROW + c * 32, (const void*)(Vhg + go));
            CP_ASYNC16(sb + SV + r * FROW + c * 32 + 16, (const void*)(Vhg + go + 8));
        }
        CP_COMMIT();
        CP_WAIT1();          // Q + K landed; V still in flight
        __syncthreads();

        // ---- S = Q K^T (2-term: (Qh+Ql) Kh) ----
        float s[8][4];
#pragma unroll
        for (int t = 0; t < 8; t++)
#pragma unroll
            for (int c = 0; c < 4; c++) s[t][c] = 0.f;
#pragma unroll
        for (int ks = 0; ks < 8; ks++) {
            uint32_t qa = sb + SQ + (w * 16 + r16) * FROW + ks * 32 + cby;
            uint32_t qh[4], ql[4], kh[4][4];
            LDSM_X4(qh[0], qh[1], qh[2], qh[3], qa);
            LDSM_X4(ql[0], ql[1], ql[2], ql[3], qa + FTILE);
#pragma unroll
            for (int g = 0; g < 4; g++) {
                uint32_t ka = sb + SK + (g * 16 + r16) * FROW + ks * 32 + cby;
                LDSM_X4(kh[g][0], kh[g][1], kh[g][2], kh[g][3], ka);
            }
#pragma unroll
            for (int t = 0; t < 8; t++) {
                int g = t >> 1, sel = t & 1;
                uint32_t bh0 = kh[g][sel], bh1 = kh[g][sel + 2];
                MMA16816(s[t], qh[0], qh[1], qh[2], qh[3], bh0, bh1);
                MMA16816(s[t], ql[0], ql[1], ql[2], ql[3], bh0, bh1);
            }
        }

        // ---- online softmax ----
        bool diag = (kt == qt);
        float mx0 = -INFINITY, mx1 = -INFINITY;
#pragma unroll
        for (int t = 0; t < 8; t++) {
            int colb = kt * 64 + t * 8 + (lane & 3) * 2;
            s[t][0] *= scale; s[t][1] *= scale; s[t][2] *= scale; s[t][3] *= scale;
            if (diag) {
                if (colb     > qrow0)     s[t][0] = -INFINITY;
                if (colb + 1 > qrow0)     s[t][1] = -INFINITY;
                if (colb     > qrow0 + 8) s[t][2] = -INFINITY;
                if (colb + 1 > qrow0 + 8) s[t][3] = -INFINITY;
            }
            mx0 = fmaxf(mx0, fmaxf(s[t][0], s[t][1]));
            mx1 = fmaxf(mx1, fmaxf(s[t][2], s[t][3]));
        }
        mx0 = fmaxf(mx0, __shfl_xor_sync(0xffffffffu, mx0, 1));
        mx0 = fmaxf(mx0, __shfl_xor_sync(0xffffffffu, mx0, 2));
        mx1 = fmaxf(mx1, __shfl_xor_sync(0xffffffffu, mx1, 1));
        mx1 = fmaxf(mx1, __shfl_xor_sync(0xffffffffu, mx1, 2));
        float mn0 = fmaxf(m0r, mx0), mn1 = fmaxf(m1r, mx1);
        float corr0 = __expf(m0r - mn0), corr1 = __expf(m1r - mn1);
        m0r = mn0; m1r = mn1;

        float sum0 = 0.f, sum1 = 0.f;
        uint32_t ph[4][4], pl[4][4];
#pragma unroll
        for (int t = 0; t < 8; t++) {
            float p0 = __expf(s[t][0] - mn0);
            float p1 = __expf(s[t][1] - mn0);
            float p2 = __expf(s[t][2] - mn1);
            float p3 = __expf(s[t][3] - mn1);
            sum0 += p0 + p1;
            sum1 += p2 + p3;
            float h0 = __half2float(__float2half_rn(p0));
            float h1 = __half2float(__float2half_rn(p1));
            float h2 = __half2float(__float2half_rn(p2));
            float h3 = __half2float(__float2half_rn(p3));
            int j = t >> 1;
            if ((t & 1) == 0) {
                ph[j][0] = pack_f16(h0, h1);
                ph[j][1] = pack_f16(h2, h3);
                pl[j][0] = pack_f16(p0 - h0, p1 - h1);
                pl[j][1] = pack_f16(p2 - h2, p3 - h3);
            } else {
                ph[j][2] = pack_f16(h0, h1);
                ph[j][3] = pack_f16(h2, h3);
                pl[j][2] = pack_f16(p0 - h0, p1 - h1);
                pl[j][3] = pack_f16(p2 - h2, p3 - h3);
            }
        }
        sum0 += __shfl_xor_sync(0xffffffffu, sum0, 1);
        sum0 += __shfl_xor_sync(0xffffffffu, sum0, 2);
        sum1 += __shfl_xor_sync(0xffffffffu, sum1, 1);
        sum1 += __shfl_xor_sync(0xffffffffu, sum1, 2);
        l0 = l0 * corr0 + sum0;
        l1 = l1 * corr1 + sum1;
#pragma unroll
        for (int t = 0; t < 16; t++) {
            o[t][0] *= corr0; o[t][1] *= corr0;
            o[t][2] *= corr1; o[t][3] *= corr1;
        }

        CP_WAIT0();          // V landed
        __syncthreads();

        // ---- O += P V (2-term: (Ph+Pl) Vh) ----
#pragma unroll
        for (int j = 0; j < 4; j++) {
#pragma unroll
            for (int g = 0; g < 8; g++) {
                uint32_t va = sb + SV + (j * 16 + r16) * FROW + g * 32 + cby;
                uint32_t vh[4];
                LDSM_X4_T(vh[0], vh[1], vh[2], vh[3], va);
                MMA16816(o[2 * g],     ph[j][0], ph[j][1], ph[j][2], ph[j][3], vh[0], vh[1]);
                MMA16816(o[2 * g],     pl[j][0], pl[j][1], pl[j][2], pl[j][3], vh[0], vh[1]);
                MMA16816(o[2 * g + 1], ph[j][0], ph[j][1], ph[j][2], ph[j][3], vh[2], vh[3]);
                MMA16816(o[2 * g + 1], pl[j][0], pl[j][1], pl[j][2], pl[j][3], vh[2], vh[3]);
            }
        }
    }

    // ---- normalize + write y split (fp16 hi/lo) ----
    float inv0 = 1.0f / l0, inv1 = 1.0f / l1;
    int grow0 = b * NT + qt * 64 + w * 16 + (lane >> 2);
#pragma unroll
    for (int t = 0; t < 16; t++) {
        int col = h * 128 + t * 8 + (lane & 3) * 2;
        float v0 = o[t][0] * inv0, v1 = o[t][1] * inv0;
        float v2 = o[t][2] * inv1, v3 = o[t][3] * inv1;
        float h0 = __half2float(__float2half_rn(v0));
        float h1 = __half2float(__float2half_rn(v1));
        float h2 = __half2float(__float2half_rn(v2));
        float h3 = __half2float(__float2half_rn(v3));
        size_t i0 = (size_t)grow0 * ND + col;
        size_t i1 = (size_t)(grow0 + 8) * ND + col;
        *(uint32_t*)&g_yh[i0] = pack_f16(h0, h1);
        *(uint32_t*)&g_yl[i0] = pack_f16(v0 - h0, v1 - h1);
        *(uint32_t*)&g_yh[i1] = pack_f16(h2, h3);
        *(uint32_t*)&g_yl[i1] = pack_f16(v2 - h2, v3 - h3);
    }
}

// ---------------- launch ------------------------------------------------------
extern "C" void kernel_launch(void* const* d_in, const int* in_sizes, int n_in,
                              void* d_out, int out_size) {
    const float* x   = (const float*)d_in[0];
    const float* wq  = (const float*)d_in[1];
    const float* wk  = (const float*)d_in[2];
    const float* wv  = (const float*)d_in[3];
    const float* wo  = (const float*)d_in[4];
    const float* qnw = (const float*)d_in[5];
    const float* knw = (const float*)d_in[6];
    float* out = (float*)d_out;

    cudaFuncSetAttribute(flash_kernel, cudaFuncAttributeMaxDynamicSharedMemorySize,
                         FLASH_SMEM);
    cudaFuncSetAttribute(gemm_mma_kernel, cudaFuncAttributeMaxDynamicSharedMemorySize,
                         GEMM_SMEM);

    rope_table_kernel<<<NT, 64>>>();
    prep_kernel<<<18432, 256>>>(x, wq, wk, wv, wo);
    gemm_mma_kernel<<<dim3(32, 24), 256, GEMM_SMEM>>>(0, nullptr);
    rope_norm_kernel<<<dim3(NB * NT, 6), 128>>>(qnw, knw);
    flash_kernel<<<dim3(NT / 64, NH, NB), 128, FLASH_SMEM>>>();
    gemm_mma_kernel<<<dim3(32, 16), 256, GEMM_SMEM>>>(1, out);
}

// round 6
// speedup vs baseline: 4.0555x; 1.1822x over previous
#include <cuda_runtime.h>
#include <cuda_fp16.h>
#include <math.h>
#include <cstdint>

#define NB 2
#define NT 2048
#define ND 2048
#define NH 16
#define NKV 4
#define HD 128

typedef __half f16;

// ---------------- scratch -----------------------------------------------------
static __device__ float g_qkv[(size_t)NB * NT * 3072];
static __device__ float g_cos[NT * 64];
static __device__ float g_sin[NT * 64];
static __device__ f16 g_xh[(size_t)NB * NT * ND], g_xl[(size_t)NB * NT * ND];
static __device__ f16 g_wh[(size_t)3072 * 2048];          // [wq;wk;wv] hi
static __device__ f16 g_woh[(size_t)2048 * 2048];
static __device__ f16 g_yh[(size_t)NB * NT * ND];
static __device__ f16 g_Qh[(size_t)NB * NH * NT * HD], g_Ql[(size_t)NB * NH * NT * HD];
static __device__ f16 g_Kh[(size_t)NB * NKV * NT * HD];
static __device__ f16 g_Vh[(size_t)NB * NKV * NT * HD];

// ---------------- PTX helpers (sm_80-compatible) ------------------------------
__device__ __forceinline__ uint32_t smem_u32(const void* p) {
    uint32_t a;
    asm("{ .reg .u64 t; cvta.to.shared.u64 t, %1; cvt.u32.u64 %0, t; }" : "=r"(a) : "l"(p));
    return a;
}
#define CP_ASYNC16(dst, src)                                                   \
    asm volatile("cp.async.cg.shared.global [%0], [%1], 16;"                   \
                 :: "r"(dst), "l"(src) : "memory")
#define CP_COMMIT() asm volatile("cp.async.commit_group;" ::: "memory")
#define CP_WAIT0()  asm volatile("cp.async.wait_group 0;" ::: "memory")
#define CP_WAIT1()  asm volatile("cp.async.wait_group 1;" ::: "memory")
#define LDSM_X4(r0, r1, r2, r3, addr)                                          \
    asm volatile("ldmatrix.sync.aligned.m8n8.x4.shared.b16 {%0,%1,%2,%3}, [%4];" \
                 : "=r"(r0), "=r"(r1), "=r"(r2), "=r"(r3) : "r"(addr))
#define LDSM_X4_T(r0, r1, r2, r3, addr)                                        \
    asm volatile("ldmatrix.sync.aligned.m8n8.x4.trans.shared.b16 {%0,%1,%2,%3}, [%4];" \
                 : "=r"(r0), "=r"(r1), "=r"(r2), "=r"(r3) : "r"(addr))
#define MMA16816(d, a0, a1, a2, a3, b0, b1)                                    \
    asm volatile("mma.sync.aligned.m16n8k16.row.col.f32.f16.f16.f32 "          \
                 "{%0,%1,%2,%3}, {%4,%5,%6,%7}, {%8,%9}, {%0,%1,%2,%3};"       \
                 : "+f"((d)[0]), "+f"((d)[1]), "+f"((d)[2]), "+f"((d)[3])      \
                 : "r"(a0), "r"(a1), "r"(a2), "r"(a3), "r"(b0), "r"(b1))

__device__ __forceinline__ uint32_t pack_f16(float a, float b) {
    __half2 t = __floats2half2_rn(a, b);
    return *(uint32_t*)&t;
}

// ---------------- RoPE table --------------------------------------------------
__global__ void rope_table_kernel() {
    int t = blockIdx.x;
    int i = threadIdx.x;  // 0..63
    double f = exp(-((double)(2 * i) / 128.0) * log(10000.0));
    double a = (double)t * f;
    g_cos[t * 64 + i] = (float)cos(a);
    g_sin[t * 64 + i] = (float)sin(a);
}

// ---------------- fused fp32 -> fp16 prep (x split; weights hi-only) ----------
__global__ __launch_bounds__(256) void prep_kernel(const float* __restrict__ x,
                                                   const float* __restrict__ wq,
                                                   const float* __restrict__ wk,
                                                   const float* __restrict__ wv,
                                                   const float* __restrict__ wo) {
    size_t i = ((size_t)blockIdx.x * 256 + threadIdx.x) * 4;
    const float* src;
    f16 *H, *L = nullptr;
    if (i < 8388608)        { src = x  + i;            H = g_xh + i; L = g_xl + i; }
    else if (i < 12582912)  { size_t o = i - 8388608;  src = wq + o; H = g_wh + o; }
    else if (i < 13631488)  { size_t o = i - 12582912; src = wk + o; H = g_wh + 4194304 + o; }
    else if (i < 14680064)  { size_t o = i - 13631488; src = wv + o; H = g_wh + 5242880 + o; }
    else                    { size_t o = i - 14680064; src = wo + o; H = g_woh + o; }

    float4 v = *(const float4*)src;
    float vv[4] = {v.x, v.y, v.z, v.w};
    f16 hv[4];
#pragma unroll
    for (int e = 0; e < 4; e++) hv[e] = __float2half_rn(vv[e]);
    *(__half2*)(H)     = __halves2half2(hv[0], hv[1]);
    *(__half2*)(H + 2) = __halves2half2(hv[2], hv[3]);
    if (L) {
        f16 lv[4];
#pragma unroll
        for (int e = 0; e < 4; e++) lv[e] = __float2half_rn(vv[e] - __half2float(hv[e]));
        *(__half2*)(L)     = __halves2half2(lv[0], lv[1]);
        *(__half2*)(L + 2) = __halves2half2(lv[2], lv[3]);
    }
}

// ---------------- split-fp16 GEMM via mma.sync --------------------------------
// NTERMS=2: C = (Ah+Al) Bh^T  (QKV).  NTERMS=1: C = Ah Bh^T  (WO).
// CTA tile 128x128, K-chunk 32, 3-stage cp.async pipeline.
// smem per buffer: (NTERMS+1) tiles of [128][40] f16 (10240B each).
template <int NTERMS>
__global__ __launch_bounds__(256) void gemm_mma_kernel(float* __restrict__ Cout) {
    constexpr int BUFSZ = (NTERMS + 1) * 10240;
    constexpr int BOFF  = NTERMS * 10240;
    extern __shared__ char smem[];
    const f16 *Ah, *Al, *Bh;
    float* C;
    int ldc;
    if (NTERMS == 2) { Ah = g_xh; Al = g_xl; Bh = g_wh;  C = g_qkv; ldc = 3072; }
    else             { Ah = g_yh; Al = nullptr; Bh = g_woh; C = Cout; ldc = 2048; }
    uint32_t sb = smem_u32(smem);
    int tid = threadIdx.x, lane = tid & 31, wid = tid >> 5;
    int wm = wid >> 1, wn = wid & 1;
    int m0 = blockIdx.x * 128, n0 = blockIdx.y * 128;

    int row = tid >> 1, half = tid & 1;
    size_t aoff0 = (size_t)(m0 + row) * 2048 + half * 16;
    size_t boff0 = (size_t)(n0 + row) * 2048 + half * 16;
    uint32_t dst0 = sb + row * 80 + half * 32;

    float acc[2][8][4];
#pragma unroll
    for (int mi = 0; mi < 2; mi++)
#pragma unroll
        for (int t = 0; t < 8; t++)
#pragma unroll
            for (int c = 0; c < 4; c++) acc[mi][t][c] = 0.f;

#define GEMM_PREFETCH(c, bsel) do {                                            \
    uint32_t d = dst0 + (bsel) * BUFSZ;                                        \
    size_t ao = aoff0 + (size_t)(c) * 32, bo = boff0 + (size_t)(c) * 32;       \
    CP_ASYNC16(d,      (const void*)(Ah + ao));                                \
    CP_ASYNC16(d + 16, (const void*)(Ah + ao + 8));                            \
    if (NTERMS == 2) {                                                         \
        CP_ASYNC16(d + 10240, (const void*)(Al + ao));                         \
        CP_ASYNC16(d + 10256, (const void*)(Al + ao + 8));                     \
    }                                                                          \
    CP_ASYNC16(d + BOFF,      (const void*)(Bh + bo));                         \
    CP_ASYNC16(d + BOFF + 16, (const void*)(Bh + bo + 8));                     \
} while (0)

    GEMM_PREFETCH(0, 0);
    CP_COMMIT();
    GEMM_PREFETCH(1, 1);
    CP_COMMIT();

    int r16 = lane & 15;
    uint32_t cby = (lane >> 4) * 16;

    for (int c = 0; c < 64; c++) {
        CP_WAIT1();
        __syncthreads();
        if (c < 62) { GEMM_PREFETCH(c + 2, (c + 2) % 3); CP_COMMIT(); }
        uint32_t base = sb + (c % 3) * BUFSZ;
#pragma unroll
        for (int ks = 0; ks < 2; ks++) {
            uint32_t ahf[2][4], alf[2][4], bhf[4][4];
#pragma unroll
            for (int mi = 0; mi < 2; mi++) {
                uint32_t ad = base + ((wm * 32 + mi * 16 + r16) * 40 + ks * 16) * 2 + cby;
                LDSM_X4(ahf[mi][0], ahf[mi][1], ahf[mi][2], ahf[mi][3], ad);
                if (NTERMS == 2)
                    LDSM_X4(alf[mi][0], alf[mi][1], alf[mi][2], alf[mi][3], ad + 10240);
            }
#pragma unroll
            for (int g = 0; g < 4; g++) {
                uint32_t bd = base + BOFF + ((wn * 64 + g * 16 + r16) * 40 + ks * 16) * 2 + cby;
                LDSM_X4(bhf[g][0], bhf[g][1], bhf[g][2], bhf[g][3], bd);
            }
#pragma unroll
            for (int mi = 0; mi < 2; mi++)
#pragma unroll
                for (int t = 0; t < 8; t++) {
                    int g = t >> 1, s = t & 1;
                    uint32_t bh0 = bhf[g][s], bh1 = bhf[g][s + 2];
                    MMA16816(acc[mi][t], ahf[mi][0], ahf[mi][1], ahf[mi][2], ahf[mi][3], bh0, bh1);
                    if (NTERMS == 2)
                        MMA16816(acc[mi][t], alf[mi][0], alf[mi][1], alf[mi][2], alf[mi][3], bh0, bh1);
                }
        }
        __syncthreads();
    }

#pragma unroll
    for (int mi = 0; mi < 2; mi++)
#pragma unroll
        for (int t = 0; t < 8; t++) {
            int r = m0 + wm * 32 + mi * 16 + (lane >> 2);
            int cc = n0 + wn * 64 + t * 8 + (lane & 3) * 2;
            *(float2*)&C[(size_t)r * ldc + cc]       = make_float2(acc[mi][t][0], acc[mi][t][1]);
            *(float2*)&C[(size_t)(r + 8) * ldc + cc] = make_float2(acc[mi][t][2], acc[mi][t][3]);
        }
}

// ---------------- RoPE + RMSNorm + transpose + split (warp per head-row) ------
// grid (NB*NT, 6), block 128 = 4 warps; r = by*4+warp: 0..15 Q, 16..19 K, 20..23 V
__global__ __launch_bounds__(128) void rope_norm_kernel(const float* __restrict__ qnw,
                                                        const float* __restrict__ knw) {
    int m = blockIdx.x;
    int w = threadIdx.x >> 5, lane = threadIdx.x & 31;
    int r = blockIdx.y * 4 + w;
    int t = m & (NT - 1);
    int b = m >> 11;
    const float* base = g_qkv + (size_t)m * 3072;
    int d0 = lane * 4;

    if (r >= 20) {  // V: fp16 hi only
        int kv = r - 20;
        float4 v = *(const float4*)(base + 2560 + kv * 128 + d0);
        size_t idx = (((size_t)(b * NKV + kv)) * NT + t) * HD + d0;
        uint2 pk = make_uint2(pack_f16(v.x, v.y), pack_f16(v.z, v.w));
        *(uint2*)&g_Vh[idx] = pk;
        return;
    }
    float4 xv;
    const float* nw;
    f16 *dh, *dl;
    size_t idx;
    if (r < 16) {
        xv = *(const float4*)(base + r * 128 + d0);
        nw = qnw;
        idx = (((size_t)(b * NH + r)) * NT + t) * HD + d0;
        dh = g_Qh; dl = g_Ql;
    } else {
        int kv = r - 16;
        xv = *(const float4*)(base + 2048 + kv * 128 + d0);
        nw = knw;
        idx = (((size_t)(b * NKV + kv)) * NT + t) * HD + d0;
        dh = g_Kh; dl = nullptr;
    }
    float2 cs0 = *(const float2*)(g_cos + t * 64 + lane * 2);
    float2 sn0 = *(const float2*)(g_sin + t * 64 + lane * 2);
    float o0 = xv.x * cs0.x - xv.y * sn0.x;
    float o1 = xv.x * sn0.x + xv.y * cs0.x;
    float o2 = xv.z * cs0.y - xv.w * sn0.y;
    float o3 = xv.z * sn0.y + xv.w * cs0.y;

    float sq = o0 * o0 + o1 * o1 + o2 * o2 + o3 * o3;
#pragma unroll
    for (int off = 16; off >= 1; off >>= 1) sq += __shfl_xor_sync(0xffffffffu, sq, off);
    float rs = rsqrtf(sq * (1.0f / 128.0f) + 1.1920929e-7f);

    float4 wv = *(const float4*)(nw + d0);
    float v0 = o0 * rs * wv.x, v1 = o1 * rs * wv.y;
    float v2 = o2 * rs * wv.z, v3 = o3 * rs * wv.w;
    f16 h0 = __float2half_rn(v0), h1 = __float2half_rn(v1);
    f16 h2 = __float2half_rn(v2), h3 = __float2half_rn(v3);
    *(uint2*)&dh[idx] = make_uint2(pack_f16(v0, v1), pack_f16(v2, v3));
    if (dl) {
        *(uint2*)&dl[idx] = make_uint2(
            pack_f16(v0 - __half2float(h0), v1 - __half2float(h1)),
            pack_f16(v2 - __half2float(h2), v3 - __half2float(h3)));
    }
}

// ---------------- flash attention via mma.sync (2-term QK, 1-term PV) --------
// 128 thr = 4 warps, BQ=64, BK=64, hd=128.
// smem: Qh,Ql,Kh,Vh each [64][136] f16 (272B rows) = 4 tiles.
#define FROW 272
#define FTILE (64 * FROW)
#define FLASH_SMEM (4 * FTILE)

__global__ __launch_bounds__(128, 2) void flash_kernel() {
    extern __shared__ char smem[];
    uint32_t sb = smem_u32(smem);
    const uint32_t SQ = 0, SK = 2 * FTILE, SV = 3 * FTILE;

    int qt = (int)gridDim.x - 1 - (int)blockIdx.x;  // long rows first
    int h = blockIdx.y, b = blockIdx.z;
    int kvh = h >> 2;
    int tid = threadIdx.x, lane = tid & 31, w = tid >> 5;

    const f16* Qhg = g_Qh + ((size_t)(b * NH + h) * NT + qt * 64) * HD;
    const f16* Qlg = g_Ql + ((size_t)(b * NH + h) * NT + qt * 64) * HD;
    const f16* Khg = g_Kh + (size_t)(b * NKV + kvh) * NT * HD;
    const f16* Vhg = g_Vh + (size_t)(b * NKV + kvh) * NT * HD;

    // Q (group 0)
#pragma unroll
    for (int i = 0; i < 8; i++) {
        int linear = i * 128 + tid;
        int r = linear >> 4, c = linear & 15;
        uint32_t d = sb + SQ + r * FROW + c * 16;
        CP_ASYNC16(d,         (const void*)(Qhg + r * HD + c * 8));
        CP_ASYNC16(d + FTILE, (const void*)(Qlg + r * HD + c * 8));
    }
    CP_COMMIT();

    float o[16][4];
#pragma unroll
    for (int t = 0; t < 16; t++)
#pragma unroll
        for (int c = 0; c < 4; c++) o[t][c] = 0.f;
    float m0r = -INFINITY, m1r = -INFINITY, l0 = 0.f, l1 = 0.f;

    const float scale = 0.08838834764831845f;
    int r16 = lane & 15;
    uint32_t cby = (lane >> 4) * 16;
    int qrow0 = qt * 64 + w * 16 + (lane >> 2);

    for (int kt = 0; kt <= qt; kt++) {
        if (kt > 0) __syncthreads();
        // K group
#pragma unroll
        for (int i = 0; i < 4; i++) {
            int linear = i * 128 + tid;
            int r = linear >> 3, c = linear & 7;
            size_t go = (size_t)(kt * 64 + r) * HD + c * 16;
            CP_ASYNC16(sb + SK + r * FROW + c * 32, (const void*)(Khg + go));
            CP_ASYNC16(sb + SK + r * FROW + c * 32 + 16, (const void*)(Khg + go + 8));
        }
        CP_COMMIT();
        // V group
#pragma unroll
        for (int i = 0; i < 4; i++) {
            int linear = i * 128 + tid;
            int r = linear >> 3, c = linear & 7;
            size_t go = (size_t)(kt * 64 + r) * HD + c * 16;
            CP_ASYNC16(sb + SV + r * FROW + c * 32, (const void*)(Vhg + go));
            CP_ASYNC16(sb + SV + r * FROW + c * 32 + 16, (const void*)(Vhg + go + 8));
        }
        CP_COMMIT();
        CP_WAIT1();          // Q + K landed; V still in flight
        __syncthreads();

        // ---- S = Q K^T (2-term: (Qh+Ql) Kh) ----
        float s[8][4];
#pragma unroll
        for (int t = 0; t < 8; t++)
#pragma unroll
            for (int c = 0; c < 4; c++) s[t][c] = 0.f;
#pragma unroll
        for (int ks = 0; ks < 8; ks++) {
            uint32_t qa = sb + SQ + (w * 16 + r16) * FROW + ks * 32 + cby;
            uint32_t qh[4], ql[4], kh[4][4];
            LDSM_X4(qh[0], qh[1], qh[2], qh[3], qa);
            LDSM_X4(ql[0], ql[1], ql[2], ql[3], qa + FTILE);
#pragma unroll
            for (int g = 0; g < 4; g++) {
                uint32_t ka = sb + SK + (g * 16 + r16) * FROW + ks * 32 + cby;
                LDSM_X4(kh[g][0], kh[g][1], kh[g][2], kh[g][3], ka);
            }
#pragma unroll
            for (int t = 0; t < 8; t++) {
                int g = t >> 1, sel = t & 1;
                uint32_t bh0 = kh[g][sel], bh1 = kh[g][sel + 2];
                MMA16816(s[t], qh[0], qh[1], qh[2], qh[3], bh0, bh1);
                MMA16816(s[t], ql[0], ql[1], ql[2], ql[3], bh0, bh1);
            }
        }

        // ---- online softmax ----
        bool diag = (kt == qt);
        float mx0 = -INFINITY, mx1 = -INFINITY;
#pragma unroll
        for (int t = 0; t < 8; t++) {
            int colb = kt * 64 + t * 8 + (lane & 3) * 2;
            s[t][0] *= scale; s[t][1] *= scale; s[t][2] *= scale; s[t][3] *= scale;
            if (diag) {
                if (colb     > qrow0)     s[t][0] = -INFINITY;
                if (colb + 1 > qrow0)     s[t][1] = -INFINITY;
                if (colb     > qrow0 + 8) s[t][2] = -INFINITY;
                if (colb + 1 > qrow0 + 8) s[t][3] = -INFINITY;
            }
            mx0 = fmaxf(mx0, fmaxf(s[t][0], s[t][1]));
            mx1 = fmaxf(mx1, fmaxf(s[t][2], s[t][3]));
        }
        mx0 = fmaxf(mx0, __shfl_xor_sync(0xffffffffu, mx0, 1));
        mx0 = fmaxf(mx0, __shfl_xor_sync(0xffffffffu, mx0, 2));
        mx1 = fmaxf(mx1, __shfl_xor_sync(0xffffffffu, mx1, 1));
        mx1 = fmaxf(mx1, __shfl_xor_sync(0xffffffffu, mx1, 2));
        float mn0 = fmaxf(m0r, mx0), mn1 = fmaxf(m1r, mx1);
        float corr0 = __expf(m0r - mn0), corr1 = __expf(m1r - mn1);
        m0r = mn0; m1r = mn1;

        float sum0 = 0.f, sum1 = 0.f;
        uint32_t ph[4][4];
#pragma unroll
        for (int t = 0; t < 8; t++) {
            float p0 = __expf(s[t][0] - mn0);
            float p1 = __expf(s[t][1] - mn0);
            float p2 = __expf(s[t][2] - mn1);
            float p3 = __expf(s[t][3] - mn1);
            sum0 += p0 + p1;
            sum1 += p2 + p3;
            int j = t >> 1;
            if ((t & 1) == 0) {
                ph[j][0] = pack_f16(p0, p1);
                ph[j][1] = pack_f16(p2, p3);
            } else {
                ph[j][2] = pack_f16(p0, p1);
                ph[j][3] = pack_f16(p2, p3);
            }
        }
        sum0 += __shfl_xor_sync(0xffffffffu, sum0, 1);
        sum0 += __shfl_xor_sync(0xffffffffu, sum0, 2);
        sum1 += __shfl_xor_sync(0xffffffffu, sum1, 1);
        sum1 += __shfl_xor_sync(0xffffffffu, sum1, 2);
        l0 = l0 * corr0 + sum0;
        l1 = l1 * corr1 + sum1;
#pragma unroll
        for (int t = 0; t < 16; t++) {
            o[t][0] *= corr0; o[t][1] *= corr0;
            o[t][2] *= corr1; o[t][3] *= corr1;
        }

        CP_WAIT0();          // V landed
        __syncthreads();

        // ---- O += P V (1-term: Ph Vh) ----
#pragma unroll
        for (int j = 0; j < 4; j++) {
#pragma unroll
            for (int g = 0; g < 8; g++) {
                uint32_t va = sb + SV + (j * 16 + r16) * FROW + g * 32 + cby;
                uint32_t vh[4];
                LDSM_X4_T(vh[0], vh[1], vh[2], vh[3], va);
                MMA16816(o[2 * g],     ph[j][0], ph[j][1], ph[j][2], ph[j][3], vh[0], vh[1]);
                MMA16816(o[2 * g + 1], ph[j][0], ph[j][1], ph[j][2], ph[j][3], vh[2], vh[3]);
            }
        }
    }

    // ---- normalize + write yh (fp16) ----
    float inv0 = 1.0f / l0, inv1 = 1.0f / l1;
    int grow0 = b * NT + qt * 64 + w * 16 + (lane >> 2);
#pragma unroll
    for (int t = 0; t < 16; t++) {
        int col = h * 128 + t * 8 + (lane & 3) * 2;
        size_t i0 = (size_t)grow0 * ND + col;
        size_t i1 = (size_t)(grow0 + 8) * ND + col;
        *(uint32_t*)&g_yh[i0] = pack_f16(o[t][0] * inv0, o[t][1] * inv0);
        *(uint32_t*)&g_yh[i1] = pack_f16(o[t][2] * inv1, o[t][3] * inv1);
    }
}

// ---------------- launch ------------------------------------------------------
extern "C" void kernel_launch(void* const* d_in, const int* in_sizes, int n_in,
                              void* d_out, int out_size) {
    const float* x   = (const float*)d_in[0];
    const float* wq  = (const float*)d_in[1];
    const float* wk  = (const float*)d_in[2];
    const float* wv  = (const float*)d_in[3];
    const float* wo  = (const float*)d_in[4];
    const float* qnw = (const float*)d_in[5];
    const float* knw = (const float*)d_in[6];
    float* out = (float*)d_out;

    cudaFuncSetAttribute(flash_kernel, cudaFuncAttributeMaxDynamicSharedMemorySize,
                         FLASH_SMEM);
    cudaFuncSetAttribute(gemm_mma_kernel<2>, cudaFuncAttributeMaxDynamicSharedMemorySize,
                         3 * 30720);
    cudaFuncSetAttribute(gemm_mma_kernel<1>, cudaFuncAttributeMaxDynamicSharedMemorySize,
                         3 * 20480);

    rope_table_kernel<<<NT, 64>>>();
    prep_kernel<<<18432, 256>>>(x, wq, wk, wv, wo);
    gemm_mma_kernel<2><<<dim3(32, 24), 256, 3 * 30720>>>(nullptr);
    rope_norm_kernel<<<dim3(NB * NT, 6), 128>>>(qnw, knw);
    flash_kernel<<<dim3(NT / 64, NH, NB), 128, FLASH_SMEM>>>();
    gemm_mma_kernel<1><<<dim3(32, 16), 256, 3 * 20480>>>(out);
}

// round 7
// speedup vs baseline: 4.3495x; 1.0725x over previous
#include <cuda_runtime.h>
#include <cuda_fp16.h>
#include <math.h>
#include <cstdint>

#define NB 2
#define NT 2048
#define ND 2048
#define NH 16
#define NKV 4
#define HD 128

typedef __half f16;

// ---------------- scratch -----------------------------------------------------
static __device__ float g_qkv[(size_t)NB * NT * 3072];
static __device__ float g_cos[NT * 64];
static __device__ float g_sin[NT * 64];
static __device__ f16 g_xh[(size_t)NB * NT * ND], g_xl[(size_t)NB * NT * ND];
static __device__ f16 g_wh[(size_t)3072 * 2048];          // [wq;wk;wv] hi
static __device__ f16 g_woh[(size_t)2048 * 2048];
static __device__ f16 g_yh[(size_t)NB * NT * ND];
static __device__ f16 g_Qh[(size_t)NB * NH * NT * HD];
static __device__ f16 g_Kh[(size_t)NB * NKV * NT * HD];
static __device__ f16 g_Vh[(size_t)NB * NKV * NT * HD];

// ---------------- PTX helpers (sm_80-compatible) ------------------------------
__device__ __forceinline__ uint32_t smem_u32(const void* p) {
    uint32_t a;
    asm("{ .reg .u64 t; cvta.to.shared.u64 t, %1; cvt.u32.u64 %0, t; }" : "=r"(a) : "l"(p));
    return a;
}
#define CP_ASYNC16(dst, src)                                                   \
    asm volatile("cp.async.cg.shared.global [%0], [%1], 16;"                   \
                 :: "r"(dst), "l"(src) : "memory")
#define CP_COMMIT() asm volatile("cp.async.commit_group;" ::: "memory")
#define CP_WAIT0()  asm volatile("cp.async.wait_group 0;" ::: "memory")
#define CP_WAIT1()  asm volatile("cp.async.wait_group 1;" ::: "memory")
#define LDSM_X4(r0, r1, r2, r3, addr)                                          \
    asm volatile("ldmatrix.sync.aligned.m8n8.x4.shared.b16 {%0,%1,%2,%3}, [%4];" \
                 : "=r"(r0), "=r"(r1), "=r"(r2), "=r"(r3) : "r"(addr))
#define LDSM_X4_T(r0, r1, r2, r3, addr)                                        \
    asm volatile("ldmatrix.sync.aligned.m8n8.x4.trans.shared.b16 {%0,%1,%2,%3}, [%4];" \
                 : "=r"(r0), "=r"(r1), "=r"(r2), "=r"(r3) : "r"(addr))
#define MMA16816(d, a0, a1, a2, a3, b0, b1)                                    \
    asm volatile("mma.sync.aligned.m16n8k16.row.col.f32.f16.f16.f32 "          \
                 "{%0,%1,%2,%3}, {%4,%5,%6,%7}, {%8,%9}, {%0,%1,%2,%3};"       \
                 : "+f"((d)[0]), "+f"((d)[1]), "+f"((d)[2]), "+f"((d)[3])      \
                 : "r"(a0), "r"(a1), "r"(a2), "r"(a3), "r"(b0), "r"(b1))

__device__ __forceinline__ uint32_t pack_f16(float a, float b) {
    __half2 t = __floats2half2_rn(a, b);
    return *(uint32_t*)&t;
}

// ---------------- RoPE table --------------------------------------------------
__global__ void rope_table_kernel() {
    int t = blockIdx.x;
    int i = threadIdx.x;  // 0..63
    double f = exp(-((double)(2 * i) / 128.0) * log(10000.0));
    double a = (double)t * f;
    g_cos[t * 64 + i] = (float)cos(a);
    g_sin[t * 64 + i] = (float)sin(a);
}

// ---------------- fused fp32 -> fp16 prep (x split; weights hi-only) ----------
__global__ __launch_bounds__(256) void prep_kernel(const float* __restrict__ x,
                                                   const float* __restrict__ wq,
                                                   const float* __restrict__ wk,
                                                   const float* __restrict__ wv,
                                                   const float* __restrict__ wo) {
    size_t i = ((size_t)blockIdx.x * 256 + threadIdx.x) * 4;
    const float* src;
    f16 *H, *L = nullptr;
    if (i < 8388608)        { src = x  + i;            H = g_xh + i; L = g_xl + i; }
    else if (i < 12582912)  { size_t o = i - 8388608;  src = wq + o; H = g_wh + o; }
    else if (i < 13631488)  { size_t o = i - 12582912; src = wk + o; H = g_wh + 4194304 + o; }
    else if (i < 14680064)  { size_t o = i - 13631488; src = wv + o; H = g_wh + 5242880 + o; }
    else                    { size_t o = i - 14680064; src = wo + o; H = g_woh + o; }

    float4 v = *(const float4*)src;
    float vv[4] = {v.x, v.y, v.z, v.w};
    f16 hv[4];
#pragma unroll
    for (int e = 0; e < 4; e++) hv[e] = __float2half_rn(vv[e]);
    *(__half2*)(H)     = __halves2half2(hv[0], hv[1]);
    *(__half2*)(H + 2) = __halves2half2(hv[2], hv[3]);
    if (L) {
        f16 lv[4];
#pragma unroll
        for (int e = 0; e < 4; e++) lv[e] = __float2half_rn(vv[e] - __half2float(hv[e]));
        *(__half2*)(L)     = __halves2half2(lv[0], lv[1]);
        *(__half2*)(L + 2) = __halves2half2(lv[2], lv[3]);
    }
}

// ---------------- split-fp16 GEMM via mma.sync --------------------------------
// NTERMS=2: C = (Ah+Al) Bh^T.  NTERMS=1: C = Ah Bh^T.
// CTA tile 128x128, K-chunk 32, 3-stage cp.async pipeline.
// smem per buffer: (NTERMS+1) tiles of [128][40] f16 (10240B each).
template <int NTERMS>
__global__ __launch_bounds__(256) void gemm_mma_kernel(const f16* __restrict__ Ah,
                                                       const f16* __restrict__ Al,
                                                       const f16* __restrict__ Bh,
                                                       float* __restrict__ C,
                                                       int ldc, int n0c) {
    constexpr int BUFSZ = (NTERMS + 1) * 10240;
    constexpr int BOFF  = NTERMS * 10240;
    extern __shared__ char smem[];
    uint32_t sb = smem_u32(smem);
    int tid = threadIdx.x, lane = tid & 31, wid = tid >> 5;
    int wm = wid >> 1, wn = wid & 1;
    int m0 = blockIdx.x * 128, n0 = blockIdx.y * 128;

    int row = tid >> 1, half = tid & 1;
    size_t aoff0 = (size_t)(m0 + row) * 2048 + half * 16;
    size_t boff0 = (size_t)(n0 + row) * 2048 + half * 16;
    uint32_t dst0 = sb + row * 80 + half * 32;

    float acc[2][8][4];
#pragma unroll
    for (int mi = 0; mi < 2; mi++)
#pragma unroll
        for (int t = 0; t < 8; t++)
#pragma unroll
            for (int c = 0; c < 4; c++) acc[mi][t][c] = 0.f;

#define GEMM_PREFETCH(c, bsel) do {                                            \
    uint32_t d = dst0 + (bsel) * BUFSZ;                                        \
    size_t ao = aoff0 + (size_t)(c) * 32, bo = boff0 + (size_t)(c) * 32;       \
    CP_ASYNC16(d,      (const void*)(Ah + ao));                                \
    CP_ASYNC16(d + 16, (const void*)(Ah + ao + 8));                            \
    if (NTERMS == 2) {                                                         \
        CP_ASYNC16(d + 10240, (const void*)(Al + ao));                         \
        CP_ASYNC16(d + 10256, (const void*)(Al + ao + 8));                     \
    }                                                                          \
    CP_ASYNC16(d + BOFF,      (const void*)(Bh + bo));                         \
    CP_ASYNC16(d + BOFF + 16, (const void*)(Bh + bo + 8));                     \
} while (0)

    GEMM_PREFETCH(0, 0);
    CP_COMMIT();
    GEMM_PREFETCH(1, 1);
    CP_COMMIT();

    int r16 = lane & 15;
    uint32_t cby = (lane >> 4) * 16;

    for (int c = 0; c < 64; c++) {
        CP_WAIT1();
        __syncthreads();
        if (c < 62) { GEMM_PREFETCH(c + 2, (c + 2) % 3); CP_COMMIT(); }
        uint32_t base = sb + (c % 3) * BUFSZ;
#pragma unroll
        for (int ks = 0; ks < 2; ks++) {
            uint32_t ahf[2][4], alf[2][4], bhf[4][4];
#pragma unroll
            for (int mi = 0; mi < 2; mi++) {
                uint32_t ad = base + ((wm * 32 + mi * 16 + r16) * 40 + ks * 16) * 2 + cby;
                LDSM_X4(ahf[mi][0], ahf[mi][1], ahf[mi][2], ahf[mi][3], ad);
                if (NTERMS == 2)
                    LDSM_X4(alf[mi][0], alf[mi][1], alf[mi][2], alf[mi][3], ad + 10240);
            }
#pragma unroll
            for (int g = 0; g < 4; g++) {
                uint32_t bd = base + BOFF + ((wn * 64 + g * 16 + r16) * 40 + ks * 16) * 2 + cby;
                LDSM_X4(bhf[g][0], bhf[g][1], bhf[g][2], bhf[g][3], bd);
            }
#pragma unroll
            for (int mi = 0; mi < 2; mi++)
#pragma unroll
                for (int t = 0; t < 8; t++) {
                    int g = t >> 1, s = t & 1;
                    uint32_t bh0 = bhf[g][s], bh1 = bhf[g][s + 2];
                    MMA16816(acc[mi][t], ahf[mi][0], ahf[mi][1], ahf[mi][2], ahf[mi][3], bh0, bh1);
                    if (NTERMS == 2)
                        MMA16816(acc[mi][t], alf[mi][0], alf[mi][1], alf[mi][2], alf[mi][3], bh0, bh1);
                }
        }
        __syncthreads();
    }

#pragma unroll
    for (int mi = 0; mi < 2; mi++)
#pragma unroll
        for (int t = 0; t < 8; t++) {
            int r = m0 + wm * 32 + mi * 16 + (lane >> 2);
            int cc = n0c + n0 + wn * 64 + t * 8 + (lane & 3) * 2;
            *(float2*)&C[(size_t)r * ldc + cc]       = make_float2(acc[mi][t][0], acc[mi][t][1]);
            *(float2*)&C[(size_t)(r + 8) * ldc + cc] = make_float2(acc[mi][t][2], acc[mi][t][3]);
        }
}

// ---------------- RoPE + RMSNorm + transpose (fp16 out) ----------------------
// grid (NB*NT, 6), block 128 = 4 warps; r = by*4+warp: 0..15 Q, 16..19 K, 20..23 V
__global__ __launch_bounds__(128) void rope_norm_kernel(const float* __restrict__ qnw,
                                                        const float* __restrict__ knw) {
    int m = blockIdx.x;
    int w = threadIdx.x >> 5, lane = threadIdx.x & 31;
    int r = blockIdx.y * 4 + w;
    int t = m & (NT - 1);
    int b = m >> 11;
    const float* base = g_qkv + (size_t)m * 3072;
    int d0 = lane * 4;

    if (r >= 20) {  // V: convert only
        int kv = r - 20;
        float4 v = *(const float4*)(base + 2560 + kv * 128 + d0);
        size_t idx = (((size_t)(b * NKV + kv)) * NT + t) * HD + d0;
        *(uint2*)&g_Vh[idx] = make_uint2(pack_f16(v.x, v.y), pack_f16(v.z, v.w));
        return;
    }
    float4 xv;
    const float* nw;
    f16* dh;
    size_t idx;
    if (r < 16) {
        xv = *(const float4*)(base + r * 128 + d0);
        nw = qnw;
        idx = (((size_t)(b * NH + r)) * NT + t) * HD + d0;
        dh = g_Qh;
    } else {
        int kv = r - 16;
        xv = *(const float4*)(base + 2048 + kv * 128 + d0);
        nw = knw;
        idx = (((size_t)(b * NKV + kv)) * NT + t) * HD + d0;
        dh = g_Kh;
    }
    float2 cs0 = *(const float2*)(g_cos + t * 64 + lane * 2);
    float2 sn0 = *(const float2*)(g_sin + t * 64 + lane * 2);
    float o0 = xv.x * cs0.x - xv.y * sn0.x;
    float o1 = xv.x * sn0.x + xv.y * cs0.x;
    float o2 = xv.z * cs0.y - xv.w * sn0.y;
    float o3 = xv.z * sn0.y + xv.w * cs0.y;

    float sq = o0 * o0 + o1 * o1 + o2 * o2 + o3 * o3;
#pragma unroll
    for (int off = 16; off >= 1; off >>= 1) sq += __shfl_xor_sync(0xffffffffu, sq, off);
    float rs = rsqrtf(sq * (1.0f / 128.0f) + 1.1920929e-7f);

    float4 wv = *(const float4*)(nw + d0);
    *(uint2*)&dh[idx] = make_uint2(pack_f16(o0 * rs * wv.x, o1 * rs * wv.y),
                                   pack_f16(o2 * rs * wv.z, o3 * rs * wv.w));
}

// ---------------- flash attention via mma.sync (1-term QK, 1-term PV) --------
// 128 thr = 4 warps, BQ=64, BK=64, hd=128.
// smem: Qh,Kh,Vh each [64][136] f16 (272B rows) = 3 tiles.
#define FROW 272
#define FTILE (64 * FROW)
#define FLASH_SMEM (3 * FTILE)

__global__ __launch_bounds__(128, 3) void flash_kernel() {
    extern __shared__ char smem[];
    uint32_t sb = smem_u32(smem);
    const uint32_t SQ = 0, SK = FTILE, SV = 2 * FTILE;

    int qt = (int)gridDim.x - 1 - (int)blockIdx.x;  // long rows first
    int h = blockIdx.y, b = blockIdx.z;
    int kvh = h >> 2;
    int tid = threadIdx.x, lane = tid & 31, w = tid >> 5;

    const f16* Qhg = g_Qh + ((size_t)(b * NH + h) * NT + qt * 64) * HD;
    const f16* Khg = g_Kh + (size_t)(b * NKV + kvh) * NT * HD;
    const f16* Vhg = g_Vh + (size_t)(b * NKV + kvh) * NT * HD;

    // Q (group 0)
#pragma unroll
    for (int i = 0; i < 4; i++) {
        int linear = i * 128 + tid;
        int r = linear >> 3, c = linear & 7;
        uint32_t d = sb + SQ + r * FROW + c * 32;
        CP_ASYNC16(d,      (const void*)(Qhg + r * HD + c * 16));
        CP_ASYNC16(d + 16, (const void*)(Qhg + r * HD + c * 16 + 8));
    }
    CP_COMMIT();

    float o[16][4];
#pragma unroll
    for (int t = 0; t < 16; t++)
#pragma unroll
        for (int c = 0; c < 4; c++) o[t][c] = 0.f;
    float m0r = -INFINITY, m1r = -INFINITY, l0 = 0.f, l1 = 0.f;

    const float scale = 0.08838834764831845f;
    int r16 = lane & 15;
    uint32_t cby = (lane >> 4) * 16;
    int qrow0 = qt * 64 + w * 16 + (lane >> 2);

    for (int kt = 0; kt <= qt; kt++) {
        if (kt > 0) __syncthreads();
        // K group
#pragma unroll
        for (int i = 0; i < 4; i++) {
            int linear = i * 128 + tid;
            int r = linear >> 3, c = linear & 7;
            size_t go = (size_t)(kt * 64 + r) * HD + c * 16;
            CP_ASYNC16(sb + SK + r * FROW + c * 32, (const void*)(Khg + go));
            CP_ASYNC16(sb + SK + r * FROW + c * 32 + 16, (const void*)(Khg + go + 8));
        }
        CP_COMMIT();
        // V group
#pragma unroll
        for (int i = 0; i < 4; i++) {
            int linear = i * 128 + tid;
            int r = linear >> 3, c = linear & 7;
            size_t go = (size_t)(kt * 64 + r) * HD + c * 16;
            CP_ASYNC16(sb + SV + r * FROW + c * 32, (const void*)(Vhg + go));
            CP_ASYNC16(sb + SV + r * FROW + c * 32 + 16, (const void*)(Vhg + go + 8));
        }
        CP_COMMIT();
        CP_WAIT1();          // Q + K landed; V still in flight
        __syncthreads();

        // ---- S = Qh Kh^T ----
        float s[8][4];
#pragma unroll
        for (int t = 0; t < 8; t++)
#pragma unroll
            for (int c = 0; c < 4; c++) s[t][c] = 0.f;
#pragma unroll
        for (int ks = 0; ks < 8; ks++) {
            uint32_t qa = sb + SQ + (w * 16 + r16) * FROW + ks * 32 + cby;
            uint32_t qh[4], kh[4][4];
            LDSM_X4(qh[0], qh[1], qh[2], qh[3], qa);
#pragma unroll
            for (int g = 0; g < 4; g++) {
                uint32_t ka = sb + SK + (g * 16 + r16) * FROW + ks * 32 + cby;
                LDSM_X4(kh[g][0], kh[g][1], kh[g][2], kh[g][3], ka);
            }
#pragma unroll
            for (int t = 0; t < 8; t++) {
                int g = t >> 1, sel = t & 1;
                MMA16816(s[t], qh[0], qh[1], qh[2], qh[3], kh[g][sel], kh[g][sel + 2]);
            }
        }

        // ---- online softmax ----
        bool diag = (kt == qt);
        float mx0 = -INFINITY, mx1 = -INFINITY;
#pragma unroll
        for (int t = 0; t < 8; t++) {
            int colb = kt * 64 + t * 8 + (lane & 3) * 2;
            s[t][0] *= scale; s[t][1] *= scale; s[t][2] *= scale; s[t][3] *= scale;
            if (diag) {
                if (colb     > qrow0)     s[t][0] = -INFINITY;
                if (colb + 1 > qrow0)     s[t][1] = -INFINITY;
                if (colb     > qrow0 + 8) s[t][2] = -INFINITY;
                if (colb + 1 > qrow0 + 8) s[t][3] = -INFINITY;
            }
            mx0 = fmaxf(mx0, fmaxf(s[t][0], s[t][1]));
            mx1 = fmaxf(mx1, fmaxf(s[t][2], s[t][3]));
        }
        mx0 = fmaxf(mx0, __shfl_xor_sync(0xffffffffu, mx0, 1));
        mx0 = fmaxf(mx0, __shfl_xor_sync(0xffffffffu, mx0, 2));
        mx1 = fmaxf(mx1, __shfl_xor_sync(0xffffffffu, mx1, 1));
        mx1 = fmaxf(mx1, __shfl_xor_sync(0xffffffffu, mx1, 2));
        float mn0 = fmaxf(m0r, mx0), mn1 = fmaxf(m1r, mx1);
        float corr0 = __expf(m0r - mn0), corr1 = __expf(m1r - mn1);
        m0r = mn0; m1r = mn1;

        float sum0 = 0.f, sum1 = 0.f;
        uint32_t ph[4][4];
#pragma unroll
        for (int t = 0; t < 8; t++) {
            float p0 = __expf(s[t][0] - mn0);
            float p1 = __expf(s[t][1] - mn0);
            float p2 = __expf(s[t][2] - mn1);
            float p3 = __expf(s[t][3] - mn1);
            sum0 += p0 + p1;
            sum1 += p2 + p3;
            int j = t >> 1;
            if ((t & 1) == 0) {
                ph[j][0] = pack_f16(p0, p1);
                ph[j][1] = pack_f16(p2, p3);
            } else {
                ph[j][2] = pack_f16(p0, p1);
                ph[j][3] = pack_f16(p2, p3);
            }
        }
        sum0 += __shfl_xor_sync(0xffffffffu, sum0, 1);
        sum0 += __shfl_xor_sync(0xffffffffu, sum0, 2);
        sum1 += __shfl_xor_sync(0xffffffffu, sum1, 1);
        sum1 += __shfl_xor_sync(0xffffffffu, sum1, 2);
        l0 = l0 * corr0 + sum0;
        l1 = l1 * corr1 + sum1;
#pragma unroll
        for (int t = 0; t < 16; t++) {
            o[t][0] *= corr0; o[t][1] *= corr0;
            o[t][2] *= corr1; o[t][3] *= corr1;
        }

        CP_WAIT0();          // V landed
        __syncthreads();

        // ---- O += Ph Vh ----
#pragma unroll
        for (int j = 0; j < 4; j++) {
#pragma unroll
            for (int g = 0; g < 8; g++) {
                uint32_t va = sb + SV + (j * 16 + r16) * FROW + g * 32 + cby;
                uint32_t vh[4];
                LDSM_X4_T(vh[0], vh[1], vh[2], vh[3], va);
                MMA16816(o[2 * g],     ph[j][0], ph[j][1], ph[j][2], ph[j][3], vh[0], vh[1]);
                MMA16816(o[2 * g + 1], ph[j][0], ph[j][1], ph[j][2], ph[j][3], vh[2], vh[3]);
            }
        }
    }

    // ---- normalize + write yh (fp16) ----
    float inv0 = 1.0f / l0, inv1 = 1.0f / l1;
    int grow0 = b * NT + qt * 64 + w * 16 + (lane >> 2);
#pragma unroll
    for (int t = 0; t < 16; t++) {
        int col = h * 128 + t * 8 + (lane & 3) * 2;
        size_t i0 = (size_t)grow0 * ND + col;
        size_t i1 = (size_t)(grow0 + 8) * ND + col;
        *(uint32_t*)&g_yh[i0] = pack_f16(o[t][0] * inv0, o[t][1] * inv0);
        *(uint32_t*)&g_yh[i1] = pack_f16(o[t][2] * inv1, o[t][3] * inv1);
    }
}

// ---------------- launch ------------------------------------------------------
extern "C" void kernel_launch(void* const* d_in, const int* in_sizes, int n_in,
                              void* d_out, int out_size) {
    const float* x   = (const float*)d_in[0];
    const float* wq  = (const float*)d_in[1];
    const float* wk  = (const float*)d_in[2];
    const float* wv  = (const float*)d_in[3];
    const float* wo  = (const float*)d_in[4];
    const float* qnw = (const float*)d_in[5];
    const float* knw = (const float*)d_in[6];
    float* out = (float*)d_out;

    cudaFuncSetAttribute(flash_kernel, cudaFuncAttributeMaxDynamicSharedMemorySize,
                         FLASH_SMEM);
    cudaFuncSetAttribute(gemm_mma_kernel<2>, cudaFuncAttributeMaxDynamicSharedMemorySize,
                         3 * 30720);
    cudaFuncSetAttribute(gemm_mma_kernel<1>, cudaFuncAttributeMaxDynamicSharedMemorySize,
                         3 * 20480);

    float* qkv_ptr;   cudaGetSymbolAddress((void**)&qkv_ptr, g_qkv);
    f16* xh_ptr;      cudaGetSymbolAddress((void**)&xh_ptr, g_xh);
    f16* xl_ptr;      cudaGetSymbolAddress((void**)&xl_ptr, g_xl);
    f16* wh_ptr;      cudaGetSymbolAddress((void**)&wh_ptr, g_wh);
    f16* woh_ptr;     cudaGetSymbolAddress((void**)&woh_ptr, g_woh);
    f16* yh_ptr;      cudaGetSymbolAddress((void**)&yh_ptr, g_yh);

    rope_table_kernel<<<NT, 64>>>();
    prep_kernel<<<18432, 256>>>(x, wq, wk, wv, wo);
    // Q,K columns (0..2559): 2-term
    gemm_mma_kernel<2><<<dim3(32, 20), 256, 3 * 30720>>>(xh_ptr, xl_ptr, wh_ptr,
                                                         qkv_ptr, 3072, 0);
    // V columns (2560..3071): 1-term
    gemm_mma_kernel<1><<<dim3(32, 4), 256, 3 * 20480>>>(xh_ptr, nullptr,
                                                        wh_ptr + (size_t)2560 * 2048,
                                                        qkv_ptr, 3072, 2560);
    rope_norm_kernel<<<dim3(NB * NT, 6), 128>>>(qnw, knw);
    flash_kernel<<<dim3(NT / 64, NH, NB), 128, FLASH_SMEM>>>();
    gemm_mma_kernel<1><<<dim3(32, 16), 256, 3 * 20480>>>(yh_ptr, nullptr, woh_ptr,
                                                         out, 2048, 0);
}

// round 8
// speedup vs baseline: 4.4209x; 1.0164x over previous
#include <cuda_runtime.h>
#include <cuda_fp16.h>
#include <math.h>
#include <cstdint>

#define NB 2
#define NT 2048
#define ND 2048
#define NH 16
#define NKV 4
#define HD 128

typedef __half f16;

// ---------------- scratch -----------------------------------------------------
static __device__ float g_qkv[(size_t)NB * NT * 3072];
static __device__ float g_cos[NT * 64];
static __device__ float g_sin[NT * 64];
static __device__ f16 g_xh[(size_t)NB * NT * ND], g_xl[(size_t)NB * NT * ND];
static __device__ f16 g_wh[(size_t)3072 * 2048];          // [wq;wk;wv] hi
static __device__ f16 g_woh[(size_t)2048 * 2048];
static __device__ f16 g_yh[(size_t)NB * NT * ND];
static __device__ f16 g_Qh[(size_t)NB * NH * NT * HD];
static __device__ f16 g_Kh[(size_t)NB * NKV * NT * HD];
static __device__ f16 g_Vh[(size_t)NB * NKV * NT * HD];

// ---------------- PTX helpers (sm_80-compatible) ------------------------------
__device__ __forceinline__ uint32_t smem_u32(const void* p) {
    uint32_t a;
    asm("{ .reg .u64 t; cvta.to.shared.u64 t, %1; cvt.u32.u64 %0, t; }" : "=r"(a) : "l"(p));
    return a;
}
#define CP_ASYNC16(dst, src)                                                   \
    asm volatile("cp.async.cg.shared.global [%0], [%1], 16;"                   \
                 :: "r"(dst), "l"(src) : "memory")
#define CP_COMMIT() asm volatile("cp.async.commit_group;" ::: "memory")
#define CP_WAIT0()  asm volatile("cp.async.wait_group 0;" ::: "memory")
#define CP_WAIT1()  asm volatile("cp.async.wait_group 1;" ::: "memory")
#define LDSM_X4(r0, r1, r2, r3, addr)                                          \
    asm volatile("ldmatrix.sync.aligned.m8n8.x4.shared.b16 {%0,%1,%2,%3}, [%4];" \
                 : "=r"(r0), "=r"(r1), "=r"(r2), "=r"(r3) : "r"(addr))
#define LDSM_X4_T(r0, r1, r2, r3, addr)                                        \
    asm volatile("ldmatrix.sync.aligned.m8n8.x4.trans.shared.b16 {%0,%1,%2,%3}, [%4];" \
                 : "=r"(r0), "=r"(r1), "=r"(r2), "=r"(r3) : "r"(addr))
#define MMA16816(d, a0, a1, a2, a3, b0, b1)                                    \
    asm volatile("mma.sync.aligned.m16n8k16.row.col.f32.f16.f16.f32 "          \
                 "{%0,%1,%2,%3}, {%4,%5,%6,%7}, {%8,%9}, {%0,%1,%2,%3};"       \
                 : "+f"((d)[0]), "+f"((d)[1]), "+f"((d)[2]), "+f"((d)[3])      \
                 : "r"(a0), "r"(a1), "r"(a2), "r"(a3), "r"(b0), "r"(b1))

__device__ __forceinline__ uint32_t pack_f16(float a, float b) {
    __half2 t = __floats2half2_rn(a, b);
    return *(uint32_t*)&t;
}

// ---------------- RoPE table --------------------------------------------------
__global__ void rope_table_kernel() {
    int t = blockIdx.x;
    int i = threadIdx.x;  // 0..63
    double f = exp(-((double)(2 * i) / 128.0) * log(10000.0));
    double a = (double)t * f;
    g_cos[t * 64 + i] = (float)cos(a);
    g_sin[t * 64 + i] = (float)sin(a);
}

// ---------------- fused fp32 -> fp16 prep (x split; weights hi-only) ----------
__global__ __launch_bounds__(256) void prep_kernel(const float* __restrict__ x,
                                                   const float* __restrict__ wq,
                                                   const float* __restrict__ wk,
                                                   const float* __restrict__ wv,
                                                   const float* __restrict__ wo) {
    size_t i = ((size_t)blockIdx.x * 256 + threadIdx.x) * 4;
    const float* src;
    f16 *H, *L = nullptr;
    if (i < 8388608)        { src = x  + i;            H = g_xh + i; L = g_xl + i; }
    else if (i < 12582912)  { size_t o = i - 8388608;  src = wq + o; H = g_wh + o; }
    else if (i < 13631488)  { size_t o = i - 12582912; src = wk + o; H = g_wh + 4194304 + o; }
    else if (i < 14680064)  { size_t o = i - 13631488; src = wv + o; H = g_wh + 5242880 + o; }
    else                    { size_t o = i - 14680064; src = wo + o; H = g_woh + o; }

    float4 v = *(const float4*)src;
    float vv[4] = {v.x, v.y, v.z, v.w};
    f16 hv[4];
#pragma unroll
    for (int e = 0; e < 4; e++) hv[e] = __float2half_rn(vv[e]);
    *(__half2*)(H)     = __halves2half2(hv[0], hv[1]);
    *(__half2*)(H + 2) = __halves2half2(hv[2], hv[3]);
    if (L) {
        f16 lv[4];
#pragma unroll
        for (int e = 0; e < 4; e++) lv[e] = __float2half_rn(vv[e] - __half2float(hv[e]));
        *(__half2*)(L)     = __halves2half2(lv[0], lv[1]);
        *(__half2*)(L + 2) = __halves2half2(lv[2], lv[3]);
    }
}

// ---------------- split-fp16 GEMM via mma.sync --------------------------------
// QKV=true: fused launch; blockIdx.y<20 -> 2-term (Q,K cols), else 1-term (V).
// QKV=false: WO, 1-term. CTA tile 128x128, K-chunk 32, 3-stage cp.async.
template <bool QKV>
__global__ __launch_bounds__(256) void gemm_mma_kernel(const f16* __restrict__ Ah,
                                                       const f16* __restrict__ Al,
                                                       const f16* __restrict__ Bh,
                                                       float* __restrict__ C,
                                                       int ldc) {
    constexpr int BUFSZ = QKV ? 30720 : 20480;
    constexpr int BOFF  = QKV ? 20480 : 10240;
    extern __shared__ char smem[];
    const bool two = QKV && (blockIdx.y < 20);
    uint32_t sb = smem_u32(smem);
    int tid = threadIdx.x, lane = tid & 31, wid = tid >> 5;
    int wm = wid >> 1, wn = wid & 1;
    int m0 = blockIdx.x * 128, n0 = blockIdx.y * 128;

    int row = tid >> 1, half = tid & 1;
    size_t aoff0 = (size_t)(m0 + row) * 2048 + half * 16;
    size_t boff0 = (size_t)(n0 + row) * 2048 + half * 16;
    uint32_t dst0 = sb + row * 80 + half * 32;

    float acc[2][8][4];
#pragma unroll
    for (int mi = 0; mi < 2; mi++)
#pragma unroll
        for (int t = 0; t < 8; t++)
#pragma unroll
            for (int c = 0; c < 4; c++) acc[mi][t][c] = 0.f;

#define GEMM_PREFETCH(c, bsel) do {                                            \
    uint32_t d = dst0 + (bsel) * BUFSZ;                                        \
    size_t ao = aoff0 + (size_t)(c) * 32, bo = boff0 + (size_t)(c) * 32;       \
    CP_ASYNC16(d,      (const void*)(Ah + ao));                                \
    CP_ASYNC16(d + 16, (const void*)(Ah + ao + 8));                            \
    if (two) {                                                                 \
        CP_ASYNC16(d + 10240, (const void*)(Al + ao));                         \
        CP_ASYNC16(d + 10256, (const void*)(Al + ao + 8));                     \
    }                                                                          \
    CP_ASYNC16(d + BOFF,      (const void*)(Bh + bo));                         \
    CP_ASYNC16(d + BOFF + 16, (const void*)(Bh + bo + 8));                     \
} while (0)

    GEMM_PREFETCH(0, 0);
    CP_COMMIT();
    GEMM_PREFETCH(1, 1);
    CP_COMMIT();

    int r16 = lane & 15;
    uint32_t cby = (lane >> 4) * 16;

    for (int c = 0; c < 64; c++) {
        CP_WAIT1();
        __syncthreads();
        if (c < 62) { GEMM_PREFETCH(c + 2, (c + 2) % 3); CP_COMMIT(); }
        uint32_t base = sb + (c % 3) * BUFSZ;
#pragma unroll
        for (int ks = 0; ks < 2; ks++) {
            uint32_t ahf[2][4], alf[2][4], bhf[4][4];
#pragma unroll
            for (int mi = 0; mi < 2; mi++) {
                uint32_t ad = base + ((wm * 32 + mi * 16 + r16) * 40 + ks * 16) * 2 + cby;
                LDSM_X4(ahf[mi][0], ahf[mi][1], ahf[mi][2], ahf[mi][3], ad);
                if (two)
                    LDSM_X4(alf[mi][0], alf[mi][1], alf[mi][2], alf[mi][3], ad + 10240);
            }
#pragma unroll
            for (int g = 0; g < 4; g++) {
                uint32_t bd = base + BOFF + ((wn * 64 + g * 16 + r16) * 40 + ks * 16) * 2 + cby;
                LDSM_X4(bhf[g][0], bhf[g][1], bhf[g][2], bhf[g][3], bd);
            }
#pragma unroll
            for (int mi = 0; mi < 2; mi++)
#pragma unroll
                for (int t = 0; t < 8; t++) {
                    int g = t >> 1, s = t & 1;
                    uint32_t bh0 = bhf[g][s], bh1 = bhf[g][s + 2];
                    MMA16816(acc[mi][t], ahf[mi][0], ahf[mi][1], ahf[mi][2], ahf[mi][3], bh0, bh1);
                    if (two)
                        MMA16816(acc[mi][t], alf[mi][0], alf[mi][1], alf[mi][2], alf[mi][3], bh0, bh1);
                }
        }
        __syncthreads();
    }

#pragma unroll
    for (int mi = 0; mi < 2; mi++)
#pragma unroll
        for (int t = 0; t < 8; t++) {
            int r = m0 + wm * 32 + mi * 16 + (lane >> 2);
            int cc = n0 + wn * 64 + t * 8 + (lane & 3) * 2;
            *(float2*)&C[(size_t)r * ldc + cc]       = make_float2(acc[mi][t][0], acc[mi][t][1]);
            *(float2*)&C[(size_t)(r + 8) * ldc + cc] = make_float2(acc[mi][t][2], acc[mi][t][3]);
        }
}

// ---------------- RoPE + RMSNorm + transpose (fp16 out) ----------------------
__global__ __launch_bounds__(128) void rope_norm_kernel(const float* __restrict__ qnw,
                                                        const float* __restrict__ knw) {
    int m = blockIdx.x;
    int w = threadIdx.x >> 5, lane = threadIdx.x & 31;
    int r = blockIdx.y * 4 + w;
    int t = m & (NT - 1);
    int b = m >> 11;
    const float* base = g_qkv + (size_t)m * 3072;
    int d0 = lane * 4;

    if (r >= 20) {  // V: convert only
        int kv = r - 20;
        float4 v = *(const float4*)(base + 2560 + kv * 128 + d0);
        size_t idx = (((size_t)(b * NKV + kv)) * NT + t) * HD + d0;
        *(uint2*)&g_Vh[idx] = make_uint2(pack_f16(v.x, v.y), pack_f16(v.z, v.w));
        return;
    }
    float4 xv;
    const float* nw;
    f16* dh;
    size_t idx;
    if (r < 16) {
        xv = *(const float4*)(base + r * 128 + d0);
        nw = qnw;
        idx = (((size_t)(b * NH + r)) * NT + t) * HD + d0;
        dh = g_Qh;
    } else {
        int kv = r - 16;
        xv = *(const float4*)(base + 2048 + kv * 128 + d0);
        nw = knw;
        idx = (((size_t)(b * NKV + kv)) * NT + t) * HD + d0;
        dh = g_Kh;
    }
    float2 cs0 = *(const float2*)(g_cos + t * 64 + lane * 2);
    float2 sn0 = *(const float2*)(g_sin + t * 64 + lane * 2);
    float o0 = xv.x * cs0.x - xv.y * sn0.x;
    float o1 = xv.x * sn0.x + xv.y * cs0.x;
    float o2 = xv.z * cs0.y - xv.w * sn0.y;
    float o3 = xv.z * sn0.y + xv.w * cs0.y;

    float sq = o0 * o0 + o1 * o1 + o2 * o2 + o3 * o3;
#pragma unroll
    for (int off = 16; off >= 1; off >>= 1) sq += __shfl_xor_sync(0xffffffffu, sq, off);
    float rs = rsqrtf(sq * (1.0f / 128.0f) + 1.1920929e-7f);

    float4 wv = *(const float4*)(nw + d0);
    *(uint2*)&dh[idx] = make_uint2(pack_f16(o0 * rs * wv.x, o1 * rs * wv.y),
                                   pack_f16(o2 * rs * wv.z, o3 * rs * wv.w));
}

// ---------------- flash attention: BQ=128, 8 warps, double-buffered K/V ------
#define FROW 272
#define QTILE (128 * FROW)     // 34816
#define KVTILE (64 * FROW)     // 17408
#define FLASH_SMEM (QTILE + 4 * KVTILE)   // 104448

__global__ __launch_bounds__(256, 2) void flash_kernel() {
    extern __shared__ char smem[];
    uint32_t sb = smem_u32(smem);

    int qt = 15 - (int)blockIdx.x;       // long causal rows first
    int h = blockIdx.y, b = blockIdx.z;
    int kvh = h >> 2;
    int tid = threadIdx.x, lane = tid & 31, w = tid >> 5;

    const f16* Qhg = g_Qh + ((size_t)(b * NH + h) * NT + qt * 128) * HD;
    const f16* Khg = g_Kh + (size_t)(b * NKV + kvh) * NT * HD;
    const f16* Vhg = g_Vh + (size_t)(b * NKV + kvh) * NT * HD;

    // Q (group 0): 128 rows
#pragma unroll
    for (int i = 0; i < 4; i++) {
        int linear = i * 256 + tid;
        int r = linear >> 3, c = linear & 7;
        uint32_t d = sb + r * FROW + c * 32;
        CP_ASYNC16(d,      (const void*)(Qhg + r * HD + c * 16));
        CP_ASYNC16(d + 16, (const void*)(Qhg + r * HD + c * 16 + 8));
    }
    CP_COMMIT();

#define LOAD_KV(kt, buf) do {                                                  \
    uint32_t kb_ = sb + QTILE + (buf) * (2 * KVTILE);                          \
    _Pragma("unroll")                                                          \
    for (int i_ = 0; i_ < 2; i_++) {                                           \
        int lin_ = i_ * 256 + tid;                                             \
        int r_ = lin_ >> 3, c_ = lin_ & 7;                                     \
        size_t go_ = (size_t)((kt) * 64 + r_) * HD + c_ * 16;                  \
        uint32_t o_ = r_ * FROW + c_ * 32;                                     \
        CP_ASYNC16(kb_ + o_,                (const void*)(Khg + go_));         \
        CP_ASYNC16(kb_ + o_ + 16,           (const void*)(Khg + go_ + 8));     \
        CP_ASYNC16(kb_ + KVTILE + o_,       (const void*)(Vhg + go_));         \
        CP_ASYNC16(kb_ + KVTILE + o_ + 16,  (const void*)(Vhg + go_ + 8));     \
    }                                                                          \
} while (0)

    LOAD_KV(0, 0);
    CP_COMMIT();

    float o[16][4];
#pragma unroll
    for (int t = 0; t < 16; t++)
#pragma unroll
        for (int c = 0; c < 4; c++) o[t][c] = 0.f;
    float m0r = -INFINITY, m1r = -INFINITY, l0 = 0.f, l1 = 0.f;

    const float scale = 0.08838834764831845f;
    int r16 = lane & 15;
    uint32_t cby = (lane >> 4) * 16;
    int qrow0 = qt * 128 + w * 16 + (lane >> 2);
    int nkt = 2 * qt + 2;

    for (int kt = 0; kt < nkt; kt++) {
        if (kt > 0) __syncthreads();     // all warps done with buffer being overwritten
        if (kt + 1 < nkt) {
            LOAD_KV(kt + 1, (kt + 1) & 1);
            CP_COMMIT();
            CP_WAIT1();                  // current tile landed; prefetch in flight
        } else {
            CP_WAIT0();
        }
        __syncthreads();

        uint32_t kb = sb + QTILE + (kt & 1) * (2 * KVTILE);
        uint32_t vb = kb + KVTILE;

        // ---- S = Qh Kh^T ----
        float s[8][4];
#pragma unroll
        for (int t = 0; t < 8; t++)
#pragma unroll
            for (int c = 0; c < 4; c++) s[t][c] = 0.f;
#pragma unroll
        for (int ks = 0; ks < 8; ks++) {
            uint32_t qa = sb + (w * 16 + r16) * FROW + ks * 32 + cby;
            uint32_t qh[4], kh[4][4];
            LDSM_X4(qh[0], qh[1], qh[2], qh[3], qa);
#pragma unroll
            for (int g = 0; g < 4; g++) {
                uint32_t ka = kb + (g * 16 + r16) * FROW + ks * 32 + cby;
                LDSM_X4(kh[g][0], kh[g][1], kh[g][2], kh[g][3], ka);
            }
#pragma unroll
            for (int t = 0; t < 8; t++) {
                int g = t >> 1, sel = t & 1;
                MMA16816(s[t], qh[0], qh[1], qh[2], qh[3], kh[g][sel], kh[g][sel + 2]);
            }
        }

        // ---- online softmax ----
        bool maskt = (kt >= 2 * qt);
        float mx0 = -INFINITY, mx1 = -INFINITY;
#pragma unroll
        for (int t = 0; t < 8; t++) {
            int colb = kt * 64 + t * 8 + (lane & 3) * 2;
            s[t][0] *= scale; s[t][1] *= scale; s[t][2] *= scale; s[t][3] *= scale;
            if (maskt) {
                if (colb     > qrow0)     s[t][0] = -INFINITY;
                if (colb + 1 > qrow0)     s[t][1] = -INFINITY;
                if (colb     > qrow0 + 8) s[t][2] = -INFINITY;
                if (colb + 1 > qrow0 + 8) s[t][3] = -INFINITY;
            }
            mx0 = fmaxf(mx0, fmaxf(s[t][0], s[t][1]));
            mx1 = fmaxf(mx1, fmaxf(s[t][2], s[t][3]));
        }
        mx0 = fmaxf(mx0, __shfl_xor_sync(0xffffffffu, mx0, 1));
        mx0 = fmaxf(mx0, __shfl_xor_sync(0xffffffffu, mx0, 2));
        mx1 = fmaxf(mx1, __shfl_xor_sync(0xffffffffu, mx1, 1));
        mx1 = fmaxf(mx1, __shfl_xor_sync(0xffffffffu, mx1, 2));
        float mn0 = fmaxf(m0r, mx0), mn1 = fmaxf(m1r, mx1);
        float corr0 = __expf(m0r - mn0), corr1 = __expf(m1r - mn1);
        m0r = mn0; m1r = mn1;

        float sum0 = 0.f, sum1 = 0.f;
        uint32_t ph[4][4];
#pragma unroll
        for (int t = 0; t < 8; t++) {
            float p0 = __expf(s[t][0] - mn0);
            float p1 = __expf(s[t][1] - mn0);
            float p2 = __expf(s[t][2] - mn1);
            float p3 = __expf(s[t][3] - mn1);
            sum0 += p0 + p1;
            sum1 += p2 + p3;
            int j = t >> 1;
            if ((t & 1) == 0) {
                ph[j][0] = pack_f16(p0, p1);
                ph[j][1] = pack_f16(p2, p3);
            } else {
                ph[j][2] = pack_f16(p0, p1);
                ph[j][3] = pack_f16(p2, p3);
            }
        }
        sum0 += __shfl_xor_sync(0xffffffffu, sum0, 1);
        sum0 += __shfl_xor_sync(0xffffffffu, sum0, 2);
        sum1 += __shfl_xor_sync(0xffffffffu, sum1, 1);
        sum1 += __shfl_xor_sync(0xffffffffu, sum1, 2);
        l0 = l0 * corr0 + sum0;
        l1 = l1 * corr1 + sum1;
#pragma unroll
        for (int t = 0; t < 16; t++) {
            o[t][0] *= corr0; o[t][1] *= corr0;
            o[t][2] *= corr1; o[t][3] *= corr1;
        }

        // ---- O += Ph Vh ----
#pragma unroll
        for (int j = 0; j < 4; j++) {
#pragma unroll
            for (int g = 0; g < 8; g++) {
                uint32_t va = vb + (j * 16 + r16) * FROW + g * 32 + cby;
                uint32_t vh[4];
                LDSM_X4_T(vh[0], vh[1], vh[2], vh[3], va);
                MMA16816(o[2 * g],     ph[j][0], ph[j][1], ph[j][2], ph[j][3], vh[0], vh[1]);
                MMA16816(o[2 * g + 1], ph[j][0], ph[j][1], ph[j][2], ph[j][3], vh[2], vh[3]);
            }
        }
    }

    // ---- normalize + write yh (fp16) ----
    float inv0 = 1.0f / l0, inv1 = 1.0f / l1;
    int grow0 = b * NT + qt * 128 + w * 16 + (lane >> 2);
#pragma unroll
    for (int t = 0; t < 16; t++) {
        int col = h * 128 + t * 8 + (lane & 3) * 2;
        size_t i0 = (size_t)grow0 * ND + col;
        size_t i1 = (size_t)(grow0 + 8) * ND + col;
        *(uint32_t*)&g_yh[i0] = pack_f16(o[t][0] * inv0, o[t][1] * inv0);
        *(uint32_t*)&g_yh[i1] = pack_f16(o[t][2] * inv1, o[t][3] * inv1);
    }
}

// ---------------- launch ------------------------------------------------------
extern "C" void kernel_launch(void* const* d_in, const int* in_sizes, int n_in,
                              void* d_out, int out_size) {
    const float* x   = (const float*)d_in[0];
    const float* wq  = (const float*)d_in[1];
    const float* wk  = (const float*)d_in[2];
    const float* wv  = (const float*)d_in[3];
    const float* wo  = (const float*)d_in[4];
    const float* qnw = (const float*)d_in[5];
    const float* knw = (const float*)d_in[6];
    float* out = (float*)d_out;

    cudaFuncSetAttribute(flash_kernel, cudaFuncAttributeMaxDynamicSharedMemorySize,
                         FLASH_SMEM);
    cudaFuncSetAttribute(gemm_mma_kernel<true>, cudaFuncAttributeMaxDynamicSharedMemorySize,
                         3 * 30720);
    cudaFuncSetAttribute(gemm_mma_kernel<false>, cudaFuncAttributeMaxDynamicSharedMemorySize,
                         3 * 20480);

    float* qkv_ptr;   cudaGetSymbolAddress((void**)&qkv_ptr, g_qkv);
    f16* xh_ptr;      cudaGetSymbolAddress((void**)&xh_ptr, g_xh);
    f16* xl_ptr;      cudaGetSymbolAddress((void**)&xl_ptr, g_xl);
    f16* wh_ptr;      cudaGetSymbolAddress((void**)&wh_ptr, g_wh);
    f16* woh_ptr;     cudaGetSymbolAddress((void**)&woh_ptr, g_woh);
    f16* yh_ptr;      cudaGetSymbolAddress((void**)&yh_ptr, g_yh);

    rope_table_kernel<<<NT, 64>>>();
    prep_kernel<<<18432, 256>>>(x, wq, wk, wv, wo);
    // fused QKV: y<20 -> 2-term (Q,K), y>=20 -> 1-term (V)
    gemm_mma_kernel<true><<<dim3(32, 24), 256, 3 * 30720>>>(xh_ptr, xl_ptr, wh_ptr,
                                                            qkv_ptr, 3072);
    rope_norm_kernel<<<dim3(NB * NT, 6), 128>>>(qnw, knw);
    flash_kernel<<<dim3(16, NH, NB), 256, FLASH_SMEM>>>();
    gemm_mma_kernel<false><<<dim3(32, 16), 256, 3 * 20480>>>(yh_ptr, nullptr, woh_ptr,
                                                             out, 2048);
}

// round 9
// speedup vs baseline: 4.5101x; 1.0202x over previous
#include <cuda_runtime.h>
#include <cuda_fp16.h>
#include <math.h>
#include <cstdint>

#define NB 2
#define NT 2048
#define ND 2048
#define NH 16
#define NKV 4
#define HD 128

typedef __half f16;

// ---------------- scratch -----------------------------------------------------
static __device__ float g_qkv[(size_t)NB * NT * 3072];
static __device__ float g_cos[NT * 64];
static __device__ float g_sin[NT * 64];
static __device__ f16 g_xh[(size_t)NB * NT * ND], g_xl[(size_t)NB * NT * ND];
static __device__ f16 g_wh[(size_t)3072 * 2048];          // [wq;wk;wv] hi
static __device__ f16 g_woh[(size_t)2048 * 2048];
static __device__ f16 g_yh[(size_t)NB * NT * ND];
static __device__ f16 g_Qh[(size_t)NB * NH * NT * HD];    // pre-scaled by 1/sqrt(128)
static __device__ f16 g_Kh[(size_t)NB * NKV * NT * HD];
static __device__ f16 g_Vh[(size_t)NB * NKV * NT * HD];

// ---------------- PTX helpers (sm_80-compatible) ------------------------------
__device__ __forceinline__ uint32_t smem_u32(const void* p) {
    uint32_t a;
    asm("{ .reg .u64 t; cvta.to.shared.u64 t, %1; cvt.u32.u64 %0, t; }" : "=r"(a) : "l"(p));
    return a;
}
#define CP_ASYNC16(dst, src)                                                   \
    asm volatile("cp.async.cg.shared.global [%0], [%1], 16;"                   \
                 :: "r"(dst), "l"(src) : "memory")
#define CP_COMMIT() asm volatile("cp.async.commit_group;" ::: "memory")
#define CP_WAIT0()  asm volatile("cp.async.wait_group 0;" ::: "memory")
#define CP_WAIT1()  asm volatile("cp.async.wait_group 1;" ::: "memory")
#define LDSM_X4(r0, r1, r2, r3, addr)                                          \
    asm volatile("ldmatrix.sync.aligned.m8n8.x4.shared.b16 {%0,%1,%2,%3}, [%4];" \
                 : "=r"(r0), "=r"(r1), "=r"(r2), "=r"(r3) : "r"(addr))
#define LDSM_X4_T(r0, r1, r2, r3, addr)                                        \
    asm volatile("ldmatrix.sync.aligned.m8n8.x4.trans.shared.b16 {%0,%1,%2,%3}, [%4];" \
                 : "=r"(r0), "=r"(r1), "=r"(r2), "=r"(r3) : "r"(addr))
#define MMA16816(d, a0, a1, a2, a3, b0, b1)                                    \
    asm volatile("mma.sync.aligned.m16n8k16.row.col.f32.f16.f16.f32 "          \
                 "{%0,%1,%2,%3}, {%4,%5,%6,%7}, {%8,%9}, {%0,%1,%2,%3};"       \
                 : "+f"((d)[0]), "+f"((d)[1]), "+f"((d)[2]), "+f"((d)[3])      \
                 : "r"(a0), "r"(a1), "r"(a2), "r"(a3), "r"(b0), "r"(b1))

__device__ __forceinline__ uint32_t pack_f16(float a, float b) {
    __half2 t = __floats2half2_rn(a, b);
    return *(uint32_t*)&t;
}

// ---------------- RoPE table --------------------------------------------------
__global__ void rope_table_kernel() {
    int t = blockIdx.x;
    int i = threadIdx.x;  // 0..63
    double f = exp(-((double)(2 * i) / 128.0) * log(10000.0));
    double a = (double)t * f;
    g_cos[t * 64 + i] = (float)cos(a);
    g_sin[t * 64 + i] = (float)sin(a);
}

// ---------------- fused fp32 -> fp16 prep (x split; weights hi-only) ----------
__global__ __launch_bounds__(256) void prep_kernel(const float* __restrict__ x,
                                                   const float* __restrict__ wq,
                                                   const float* __restrict__ wk,
                                                   const float* __restrict__ wv,
                                                   const float* __restrict__ wo) {
    size_t i = ((size_t)blockIdx.x * 256 + threadIdx.x) * 4;
    const float* src;
    f16 *H, *L = nullptr;
    if (i < 8388608)        { src = x  + i;            H = g_xh + i; L = g_xl + i; }
    else if (i < 12582912)  { size_t o = i - 8388608;  src = wq + o; H = g_wh + o; }
    else if (i < 13631488)  { size_t o = i - 12582912; src = wk + o; H = g_wh + 4194304 + o; }
    else if (i < 14680064)  { size_t o = i - 13631488; src = wv + o; H = g_wh + 5242880 + o; }
    else                    { size_t o = i - 14680064; src = wo + o; H = g_woh + o; }

    float4 v = *(const float4*)src;
    float vv[4] = {v.x, v.y, v.z, v.w};
    f16 hv[4];
#pragma unroll
    for (int e = 0; e < 4; e++) hv[e] = __float2half_rn(vv[e]);
    *(__half2*)(H)     = __halves2half2(hv[0], hv[1]);
    *(__half2*)(H + 2) = __halves2half2(hv[2], hv[3]);
    if (L) {
        f16 lv[4];
#pragma unroll
        for (int e = 0; e < 4; e++) lv[e] = __float2half_rn(vv[e] - __half2float(hv[e]));
        *(__half2*)(L)     = __halves2half2(lv[0], lv[1]);
        *(__half2*)(L + 2) = __halves2half2(lv[2], lv[3]);
    }
}

// ---------------- split-fp16 GEMM via mma.sync --------------------------------
// QKV=true: fused launch; blockIdx.y<20 -> 2-term (Q,K cols), else 1-term (V).
// QKV=false: WO, 1-term. CTA tile 128x128, K-chunk 32, 3-stage cp.async.
template <bool QKV>
__global__ __launch_bounds__(256) void gemm_mma_kernel(const f16* __restrict__ Ah,
                                                       const f16* __restrict__ Al,
                                                       const f16* __restrict__ Bh,
                                                       float* __restrict__ C,
                                                       int ldc) {
    constexpr int BUFSZ = QKV ? 30720 : 20480;
    constexpr int BOFF  = QKV ? 20480 : 10240;
    extern __shared__ char smem[];
    const bool two = QKV && (blockIdx.y < 20);
    uint32_t sb = smem_u32(smem);
    int tid = threadIdx.x, lane = tid & 31, wid = tid >> 5;
    int wm = wid >> 1, wn = wid & 1;
    int m0 = blockIdx.x * 128, n0 = blockIdx.y * 128;

    int row = tid >> 1, half = tid & 1;
    size_t aoff0 = (size_t)(m0 + row) * 2048 + half * 16;
    size_t boff0 = (size_t)(n0 + row) * 2048 + half * 16;
    uint32_t dst0 = sb + row * 80 + half * 32;

    float acc[2][8][4];
#pragma unroll
    for (int mi = 0; mi < 2; mi++)
#pragma unroll
        for (int t = 0; t < 8; t++)
#pragma unroll
            for (int c = 0; c < 4; c++) acc[mi][t][c] = 0.f;

#define GEMM_PREFETCH(c, bsel) do {                                            \
    uint32_t d = dst0 + (bsel) * BUFSZ;                                        \
    size_t ao = aoff0 + (size_t)(c) * 32, bo = boff0 + (size_t)(c) * 32;       \
    CP_ASYNC16(d,      (const void*)(Ah + ao));                                \
    CP_ASYNC16(d + 16, (const void*)(Ah + ao + 8));                            \
    if (two) {                                                                 \
        CP_ASYNC16(d + 10240, (const void*)(Al + ao));                         \
        CP_ASYNC16(d + 10256, (const void*)(Al + ao + 8));                     \
    }                                                                          \
    CP_ASYNC16(d + BOFF,      (const void*)(Bh + bo));                         \
    CP_ASYNC16(d + BOFF + 16, (const void*)(Bh + bo + 8));                     \
} while (0)

    GEMM_PREFETCH(0, 0);
    CP_COMMIT();
    GEMM_PREFETCH(1, 1);
    CP_COMMIT();

    int r16 = lane & 15;
    uint32_t cby = (lane >> 4) * 16;

    for (int c = 0; c < 64; c++) {
        CP_WAIT1();
        __syncthreads();
        if (c < 62) { GEMM_PREFETCH(c + 2, (c + 2) % 3); CP_COMMIT(); }
        uint32_t base = sb + (c % 3) * BUFSZ;
#pragma unroll
        for (int ks = 0; ks < 2; ks++) {
            uint32_t ahf[2][4], alf[2][4], bhf[4][4];
#pragma unroll
            for (int mi = 0; mi < 2; mi++) {
                uint32_t ad = base + ((wm * 32 + mi * 16 + r16) * 40 + ks * 16) * 2 + cby;
                LDSM_X4(ahf[mi][0], ahf[mi][1], ahf[mi][2], ahf[mi][3], ad);
                if (two)
                    LDSM_X4(alf[mi][0], alf[mi][1], alf[mi][2], alf[mi][3], ad + 10240);
            }
#pragma unroll
            for (int g = 0; g < 4; g++) {
                uint32_t bd = base + BOFF + ((wn * 64 + g * 16 + r16) * 40 + ks * 16) * 2 + cby;
                LDSM_X4(bhf[g][0], bhf[g][1], bhf[g][2], bhf[g][3], bd);
            }
#pragma unroll
            for (int mi = 0; mi < 2; mi++)
#pragma unroll
                for (int t = 0; t < 8; t++) {
                    int g = t >> 1, s = t & 1;
                    uint32_t bh0 = bhf[g][s], bh1 = bhf[g][s + 2];
                    MMA16816(acc[mi][t], ahf[mi][0], ahf[mi][1], ahf[mi][2], ahf[mi][3], bh0, bh1);
                    if (two)
                        MMA16816(acc[mi][t], alf[mi][0], alf[mi][1], alf[mi][2], alf[mi][3], bh0, bh1);
                }
        }
        __syncthreads();
    }

#pragma unroll
    for (int mi = 0; mi < 2; mi++)
#pragma unroll
        for (int t = 0; t < 8; t++) {
            int r = m0 + wm * 32 + mi * 16 + (lane >> 2);
            int cc = n0 + wn * 64 + t * 8 + (lane & 3) * 2;
            *(float2*)&C[(size_t)r * ldc + cc]       = make_float2(acc[mi][t][0], acc[mi][t][1]);
            *(float2*)&C[(size_t)(r + 8) * ldc + cc] = make_float2(acc[mi][t][2], acc[mi][t][3]);
        }
}

// ---------------- RoPE + RMSNorm + transpose (fp16 out; q pre-scaled) ---------
__global__ __launch_bounds__(128) void rope_norm_kernel(const float* __restrict__ qnw,
                                                        const float* __restrict__ knw) {
    int m = blockIdx.x;
    int w = threadIdx.x >> 5, lane = threadIdx.x & 31;
    int r = blockIdx.y * 4 + w;
    int t = m & (NT - 1);
    int b = m >> 11;
    const float* base = g_qkv + (size_t)m * 3072;
    int d0 = lane * 4;

    if (r >= 20) {  // V: convert only
        int kv = r - 20;
        float4 v = *(const float4*)(base + 2560 + kv * 128 + d0);
        size_t idx = (((size_t)(b * NKV + kv)) * NT + t) * HD + d0;
        *(uint2*)&g_Vh[idx] = make_uint2(pack_f16(v.x, v.y), pack_f16(v.z, v.w));
        return;
    }
    float4 xv;
    const float* nw;
    f16* dh;
    size_t idx;
    float sc;
    if (r < 16) {
        xv = *(const float4*)(base + r * 128 + d0);
        nw = qnw;
        idx = (((size_t)(b * NH + r)) * NT + t) * HD + d0;
        dh = g_Qh;
        sc = 0.08838834764831845f;   // fold 1/sqrt(128) into q
    } else {
        int kv = r - 16;
        xv = *(const float4*)(base + 2048 + kv * 128 + d0);
        nw = knw;
        idx = (((size_t)(b * NKV + kv)) * NT + t) * HD + d0;
        dh = g_Kh;
        sc = 1.0f;
    }
    float2 cs0 = *(const float2*)(g_cos + t * 64 + lane * 2);
    float2 sn0 = *(const float2*)(g_sin + t * 64 + lane * 2);
    float o0 = xv.x * cs0.x - xv.y * sn0.x;
    float o1 = xv.x * sn0.x + xv.y * cs0.x;
    float o2 = xv.z * cs0.y - xv.w * sn0.y;
    float o3 = xv.z * sn0.y + xv.w * cs0.y;

    float sq = o0 * o0 + o1 * o1 + o2 * o2 + o3 * o3;
#pragma unroll
    for (int off = 16; off >= 1; off >>= 1) sq += __shfl_xor_sync(0xffffffffu, sq, off);
    float rs = rsqrtf(sq * (1.0f / 128.0f) + 1.1920929e-7f) * sc;

    float4 wv = *(const float4*)(nw + d0);
    *(uint2*)&dh[idx] = make_uint2(pack_f16(o0 * rs * wv.x, o1 * rs * wv.y),
                                   pack_f16(o2 * rs * wv.z, o3 * rs * wv.w));
}

// ---------------- flash attention: fixed-max softmax (|s|<=11.31 bound) -------
#define FROW 272
#define QTILE (128 * FROW)     // 34816
#define KVTILE (64 * FROW)     // 17408
#define FLASH_SMEM (QTILE + 4 * KVTILE)   // 104448

__global__ __launch_bounds__(256, 2) void flash_kernel() {
    extern __shared__ char smem[];
    uint32_t sb = smem_u32(smem);

    int qt = 15 - (int)blockIdx.x;       // long causal rows first
    int h = blockIdx.y, b = blockIdx.z;
    int kvh = h >> 2;
    int tid = threadIdx.x, lane = tid & 31, w = tid >> 5;

    const f16* Qhg = g_Qh + ((size_t)(b * NH + h) * NT + qt * 128) * HD;
    const f16* Khg = g_Kh + (size_t)(b * NKV + kvh) * NT * HD;
    const f16* Vhg = g_Vh + (size_t)(b * NKV + kvh) * NT * HD;

    // Q (group 0): 128 rows
#pragma unroll
    for (int i = 0; i < 4; i++) {
        int linear = i * 256 + tid;
        int r = linear >> 3, c = linear & 7;
        uint32_t d = sb + r * FROW + c * 32;
        CP_ASYNC16(d,      (const void*)(Qhg + r * HD + c * 16));
        CP_ASYNC16(d + 16, (const void*)(Qhg + r * HD + c * 16 + 8));
    }
    CP_COMMIT();

#define LOAD_KV(kt, buf) do {                                                  \
    uint32_t kb_ = sb + QTILE + (buf) * (2 * KVTILE);                          \
    _Pragma("unroll")                                                          \
    for (int i_ = 0; i_ < 2; i_++) {                                           \
        int lin_ = i_ * 256 + tid;                                             \
        int r_ = lin_ >> 3, c_ = lin_ & 7;                                     \
        size_t go_ = (size_t)((kt) * 64 + r_) * HD + c_ * 16;                  \
        uint32_t o_ = r_ * FROW + c_ * 32;                                     \
        CP_ASYNC16(kb_ + o_,                (const void*)(Khg + go_));         \
        CP_ASYNC16(kb_ + o_ + 16,           (const void*)(Khg + go_ + 8));     \
        CP_ASYNC16(kb_ + KVTILE + o_,       (const void*)(Vhg + go_));         \
        CP_ASYNC16(kb_ + KVTILE + o_ + 16,  (const void*)(Vhg + go_ + 8));     \
    }                                                                          \
} while (0)

    LOAD_KV(0, 0);
    CP_COMMIT();

    float o[16][4];
#pragma unroll
    for (int t = 0; t < 16; t++)
#pragma unroll
        for (int c = 0; c < 4; c++) o[t][c] = 0.f;
    float l0 = 0.f, l1 = 0.f;      // running (unnormalized) softmax denominators

    int r16 = lane & 15;
    uint32_t cby = (lane >> 4) * 16;
    int qrow0 = qt * 128 + w * 16 + (lane >> 2);
    int nkt = 2 * qt + 2;

    for (int kt = 0; kt < nkt; kt++) {
        if (kt > 0) __syncthreads();
        if (kt + 1 < nkt) {
            LOAD_KV(kt + 1, (kt + 1) & 1);
            CP_COMMIT();
            CP_WAIT1();
        } else {
            CP_WAIT0();
        }
        __syncthreads();

        uint32_t kb = sb + QTILE + (kt & 1) * (2 * KVTILE);
        uint32_t vb = kb + KVTILE;

        // ---- S = Qh Kh^T (q pre-scaled) ----
        float s[8][4];
#pragma unroll
        for (int t = 0; t < 8; t++)
#pragma unroll
            for (int c = 0; c < 4; c++) s[t][c] = 0.f;
#pragma unroll
        for (int ks = 0; ks < 8; ks++) {
            uint32_t qa = sb + (w * 16 + r16) * FROW + ks * 32 + cby;
            uint32_t qh[4], kh[4][4];
            LDSM_X4(qh[0], qh[1], qh[2], qh[3], qa);
#pragma unroll
            for (int g = 0; g < 4; g++) {
                uint32_t ka = kb + (g * 16 + r16) * FROW + ks * 32 + cby;
                LDSM_X4(kh[g][0], kh[g][1], kh[g][2], kh[g][3], ka);
            }
#pragma unroll
            for (int t = 0; t < 8; t++) {
                int g = t >> 1, sel = t & 1;
                MMA16816(s[t], qh[0], qh[1], qh[2], qh[3], kh[g][sel], kh[g][sel + 2]);
            }
        }

        // ---- fixed-max softmax: p = exp(s - 2), no max tracking, no rescale --
        bool maskt = (kt >= 2 * qt);
        uint32_t ph[4][4];
#pragma unroll
        for (int t = 0; t < 8; t++) {
            if (maskt) {
                int colb = kt * 64 + t * 8 + (lane & 3) * 2;
                if (colb     > qrow0)     s[t][0] = -INFINITY;
                if (colb + 1 > qrow0)     s[t][1] = -INFINITY;
                if (colb     > qrow0 + 8) s[t][2] = -INFINITY;
                if (colb + 1 > qrow0 + 8) s[t][3] = -INFINITY;
            }
            float p0 = __expf(s[t][0] - 2.0f);
            float p1 = __expf(s[t][1] - 2.0f);
            float p2 = __expf(s[t][2] - 2.0f);
            float p3 = __expf(s[t][3] - 2.0f);
            uint32_t pk01 = pack_f16(p0, p1);
            uint32_t pk23 = pack_f16(p2, p3);
            // consistent l: sum the fp16-rounded values
            float2 f01 = __half22float2(*(__half2*)&pk01);
            float2 f23 = __half22float2(*(__half2*)&pk23);
            l0 += f01.x + f01.y;
            l1 += f23.x + f23.y;
            int j = t >> 1;
            if ((t & 1) == 0) { ph[j][0] = pk01; ph[j][1] = pk23; }
            else              { ph[j][2] = pk01; ph[j][3] = pk23; }
        }

        // ---- O += Ph Vh ----
#pragma unroll
        for (int j = 0; j < 4; j++) {
#pragma unroll
            for (int g = 0; g < 8; g++) {
                uint32_t va = vb + (j * 16 + r16) * FROW + g * 32 + cby;
                uint32_t vh[4];
                LDSM_X4_T(vh[0], vh[1], vh[2], vh[3], va);
                MMA16816(o[2 * g],     ph[j][0], ph[j][1], ph[j][2], ph[j][3], vh[0], vh[1]);
                MMA16816(o[2 * g + 1], ph[j][0], ph[j][1], ph[j][2], ph[j][3], vh[2], vh[3]);
            }
        }
    }

    // ---- final l reduction (once) + normalize + write yh ----
    l0 += __shfl_xor_sync(0xffffffffu, l0, 1);
    l0 += __shfl_xor_sync(0xffffffffu, l0, 2);
    l1 += __shfl_xor_sync(0xffffffffu, l1, 1);
    l1 += __shfl_xor_sync(0xffffffffu, l1, 2);
    float inv0 = 1.0f / l0, inv1 = 1.0f / l1;
    int grow0 = b * NT + qt * 128 + w * 16 + (lane >> 2);
#pragma unroll
    for (int t = 0; t < 16; t++) {
        int col = h * 128 + t * 8 + (lane & 3) * 2;
        size_t i0 = (size_t)grow0 * ND + col;
        size_t i1 = (size_t)(grow0 + 8) * ND + col;
        *(uint32_t*)&g_yh[i0] = pack_f16(o[t][0] * inv0, o[t][1] * inv0);
        *(uint32_t*)&g_yh[i1] = pack_f16(o[t][2] * inv1, o[t][3] * inv1);
    }
}

// ---------------- launch ------------------------------------------------------
extern "C" void kernel_launch(void* const* d_in, const int* in_sizes, int n_in,
                              void* d_out, int out_size) {
    const float* x   = (const float*)d_in[0];
    const float* wq  = (const float*)d_in[1];
    const float* wk  = (const float*)d_in[2];
    const float* wv  = (const float*)d_in[3];
    const float* wo  = (const float*)d_in[4];
    const float* qnw = (const float*)d_in[5];
    const float* knw = (const float*)d_in[6];
    float* out = (float*)d_out;

    cudaFuncSetAttribute(flash_kernel, cudaFuncAttributeMaxDynamicSharedMemorySize,
                         FLASH_SMEM);
    cudaFuncSetAttribute(gemm_mma_kernel<true>, cudaFuncAttributeMaxDynamicSharedMemorySize,
                         3 * 30720);
    cudaFuncSetAttribute(gemm_mma_kernel<false>, cudaFuncAttributeMaxDynamicSharedMemorySize,
                         3 * 20480);

    float* qkv_ptr;   cudaGetSymbolAddress((void**)&qkv_ptr, g_qkv);
    f16* xh_ptr;      cudaGetSymbolAddress((void**)&xh_ptr, g_xh);
    f16* xl_ptr;      cudaGetSymbolAddress((void**)&xl_ptr, g_xl);
    f16* wh_ptr;      cudaGetSymbolAddress((void**)&wh_ptr, g_wh);
    f16* woh_ptr;     cudaGetSymbolAddress((void**)&woh_ptr, g_woh);
    f16* yh_ptr;      cudaGetSymbolAddress((void**)&yh_ptr, g_yh);

    rope_table_kernel<<<NT, 64>>>();
    prep_kernel<<<18432, 256>>>(x, wq, wk, wv, wo);
    // fused QKV: y<20 -> 2-term (Q,K), y>=20 -> 1-term (V)
    gemm_mma_kernel<true><<<dim3(32, 24), 256, 3 * 30720>>>(xh_ptr, xl_ptr, wh_ptr,
                                                            qkv_ptr, 3072);
    rope_norm_kernel<<<dim3(NB * NT, 6), 128>>>(qnw, knw);
    flash_kernel<<<dim3(16, NH, NB), 256, FLASH_SMEM>>>();
    gemm_mma_kernel<false><<<dim3(32, 16), 256, 3 * 20480>>>(yh_ptr, nullptr, woh_ptr,
                                                             out, 2048);
}